// round 1
// baseline (speedup 1.0000x reference)
#include <cuda_runtime.h>
#include <cuda_bf16.h>
#include <math.h>

#define NN 50000
#define EE 800000
#define DD 128
#define HH 8
#define CC 16
#define LL 3
#define ET (EE + NN)   // 850000 edges incl. self-loops
#define SLOPE 0.2f
#define LN_EPS 1e-5f

// ---------------- scratch (static device globals; no allocation allowed) ----
__device__ float g_h[NN * DD];       // evolving node features
__device__ float g_xl[NN * DD];      // h @ Wl
__device__ float g_xr[NN * DD];      // h @ Wr
__device__ float g_out[NN * DD];     // segment-sum accumulator (+bias)
__device__ float g_m[NN * HH];       // segment max
__device__ float g_denom[NN * HH];   // segment sum of exp
__device__ float g_ex[ET * HH];      // per-edge logits, then exp values

// ---------------- helpers ---------------------------------------------------
__device__ __forceinline__ float lrelu(float x) {
    return x > 0.f ? x : SLOPE * x;
}

__device__ __forceinline__ void atomicMaxFloat(float* addr, float val) {
    if (val >= 0.f) {
        atomicMax((int*)addr, __float_as_int(val));
    } else {
        atomicMin((unsigned int*)addr, (unsigned int)__float_as_int(val));
    }
}

// ---------------- GEMM: Y[M,128] = X[M,128] @ W[128,128] --------------------
// Block: 256 threads, tile 64 rows x 128 cols, each thread 4x8 outputs.
__global__ void gemm128(const float* __restrict__ W, int target, int use_h_input) {
    __shared__ float Xs[64][17];     // padded to kill bank conflicts
    __shared__ float Ws[16][128];

    const float* __restrict__ X = g_h;  // input always g_h here
    float* __restrict__ Y = target ? g_xr : g_xl;
    (void)use_h_input;

    int tid = threadIdx.x;
    int tx = tid & 15;   // col group (8 cols)
    int ty = tid >> 4;   // row group (4 rows)
    int row0 = blockIdx.x * 64;

    float acc[4][8];
#pragma unroll
    for (int i = 0; i < 4; i++)
#pragma unroll
        for (int j = 0; j < 8; j++) acc[i][j] = 0.f;

    for (int k0 = 0; k0 < 128; k0 += 16) {
        {   // load X tile 64x16
            int k = tid & 15;
            int rbase = tid >> 4;
#pragma unroll
            for (int j = 0; j < 4; j++) {
                int r = rbase + j * 16;
                int gr = row0 + r;
                Xs[r][k] = (gr < NN) ? X[gr * 128 + k0 + k] : 0.f;
            }
        }
        {   // load W tile 16x128
            int c = tid & 127;
            int kb = tid >> 7;   // 0..1
#pragma unroll
            for (int j = 0; j < 8; j++) {
                int k = kb + j * 2;
                Ws[k][c] = W[(k0 + k) * 128 + c];
            }
        }
        __syncthreads();
#pragma unroll
        for (int kk = 0; kk < 16; kk++) {
            float a[4], b[8];
#pragma unroll
            for (int i = 0; i < 4; i++) a[i] = Xs[ty * 4 + i][kk];
#pragma unroll
            for (int j = 0; j < 8; j++) b[j] = Ws[kk][tx * 8 + j];
#pragma unroll
            for (int i = 0; i < 4; i++)
#pragma unroll
                for (int j = 0; j < 8; j++) acc[i][j] += a[i] * b[j];
        }
        __syncthreads();
    }

#pragma unroll
    for (int i = 0; i < 4; i++) {
        int gr = row0 + ty * 4 + i;
        if (gr < NN) {
#pragma unroll
            for (int j = 0; j < 8; j++)
                Y[gr * 128 + tx * 8 + j] = acc[i][j];
        }
    }
}

// ---------------- per-layer init: out=bias, m=-inf, denom=0 -----------------
__global__ void init_layer(const float* __restrict__ bias_l) {
    int i = blockIdx.x * blockDim.x + threadIdx.x;
    if (i < NN * DD) g_out[i] = bias_l[i & 127];
    if (i < NN * HH) {
        g_m[i] = -INFINITY;
        g_denom[i] = 0.f;
    }
}

// ---------------- pass A: logits + segment max ------------------------------
// one warp per edge; lane handles 4 channels; 4 lanes per head
__global__ void edge_logits(const int* __restrict__ ei,
                            const float* __restrict__ att_l) {
    int e = blockIdx.x * 8 + (threadIdx.x >> 5);
    if (e >= ET) return;
    int lane = threadIdx.x & 31;
    int src, dst;
    if (e < EE) { src = ei[e]; dst = ei[EE + e]; }
    else        { src = e - EE; dst = src; }

    int c0 = lane * 4;
    float4 a = *(const float4*)(g_xl + src * 128 + c0);
    float4 b = *(const float4*)(g_xr + dst * 128 + c0);
    float4 t = *(const float4*)(att_l + c0);

    float s = lrelu(a.x + b.x) * t.x + lrelu(a.y + b.y) * t.y +
              lrelu(a.z + b.z) * t.z + lrelu(a.w + b.w) * t.w;
    s += __shfl_xor_sync(0xffffffffu, s, 1);
    s += __shfl_xor_sync(0xffffffffu, s, 2);

    if ((lane & 3) == 0) {
        int h = lane >> 2;
        g_ex[e * HH + h] = s;                // store raw logit
        atomicMaxFloat(&g_m[dst * HH + h], s);
    }
}

// ---------------- pass B: exp + segment sum ---------------------------------
__global__ void edge_exp(const int* __restrict__ ei) {
    int i = blockIdx.x * blockDim.x + threadIdx.x;
    if (i >= ET * HH) return;
    int e = i >> 3;
    int h = i & 7;
    int dst = (e < EE) ? ei[EE + e] : (e - EE);
    float v = __expf(g_ex[i] - g_m[dst * HH + h]);
    g_ex[i] = v;
    atomicAdd(&g_denom[dst * HH + h], v);
}

// ---------------- pass C: alpha-weighted scatter-add ------------------------
__global__ void edge_aggregate(const int* __restrict__ ei) {
    int e = blockIdx.x * 8 + (threadIdx.x >> 5);
    if (e >= ET) return;
    int lane = threadIdx.x & 31;
    int src, dst;
    if (e < EE) { src = ei[e]; dst = ei[EE + e]; }
    else        { src = e - EE; dst = src; }

    int h = lane >> 2;
    float alpha = g_ex[e * HH + h] / g_denom[dst * HH + h];
    int c0 = lane * 4;
    float4 a = *(const float4*)(g_xl + src * 128 + c0);
    float* o = g_out + dst * 128 + c0;
    atomicAdd(o + 0, alpha * a.x);
    atomicAdd(o + 1, alpha * a.y);
    atomicAdd(o + 2, alpha * a.z);
    atomicAdd(o + 3, alpha * a.w);
}

// ---------------- LayerNorm + ELU + residual --------------------------------
__global__ void finalize(const float* __restrict__ gamma_l,
                         const float* __restrict__ beta_l,
                         float* __restrict__ final_out) {
    int n = blockIdx.x * (blockDim.x >> 5) + (threadIdx.x >> 5);
    if (n >= NN) return;
    int lane = threadIdx.x & 31;
    int c0 = lane * 4;

    float4 y = *(const float4*)(g_out + n * 128 + c0);
    float sum = y.x + y.y + y.z + y.w;
#pragma unroll
    for (int o = 16; o; o >>= 1) sum += __shfl_xor_sync(0xffffffffu, sum, o);
    float mu = sum * (1.f / 128.f);

    float dx = y.x - mu, dy = y.y - mu, dz = y.z - mu, dw = y.w - mu;
    float vs = dx * dx + dy * dy + dz * dz + dw * dw;
#pragma unroll
    for (int o = 16; o; o >>= 1) vs += __shfl_xor_sync(0xffffffffu, vs, o);
    float rstd = rsqrtf(vs * (1.f / 128.f) + LN_EPS);

    float4 g = *(const float4*)(gamma_l + c0);
    float4 bb = *(const float4*)(beta_l + c0);
    float4 hv = *(const float4*)(g_h + n * 128 + c0);

    float t;
    float4 r;
    t = dx * rstd * g.x + bb.x; r.x = hv.x + (t > 0.f ? t : expm1f(t));
    t = dy * rstd * g.y + bb.y; r.y = hv.y + (t > 0.f ? t : expm1f(t));
    t = dz * rstd * g.z + bb.z; r.z = hv.z + (t > 0.f ? t : expm1f(t));
    t = dw * rstd * g.w + bb.w; r.w = hv.w + (t > 0.f ? t : expm1f(t));

    *(float4*)(g_h + n * 128 + c0) = r;
    if (final_out) *(float4*)(final_out + n * 128 + c0) = r;
}

// ---------------- host orchestration ----------------------------------------
extern "C" void kernel_launch(void* const* d_in, const int* in_sizes, int n_in,
                              void* d_out, int out_size) {
    const float* x     = (const float*)d_in[0];
    const float* Wl    = (const float*)d_in[1];
    const float* Wr    = (const float*)d_in[2];
    const float* att   = (const float*)d_in[3];
    const float* bias  = (const float*)d_in[4];
    const float* gamma = (const float*)d_in[5];
    const float* beta  = (const float*)d_in[6];
    const int*   ei    = (const int*)d_in[7];
    float* out = (float*)d_out;

    void* h_ptr = nullptr;
    cudaGetSymbolAddress(&h_ptr, g_h);
    cudaMemcpyAsync(h_ptr, x, (size_t)NN * DD * sizeof(float),
                    cudaMemcpyDeviceToDevice);

    const int gemm_grid  = (NN + 63) / 64;
    const int init_grid  = (NN * DD + 255) / 256;
    const int edge_grid  = (ET + 7) / 8;
    const int exp_grid   = (ET * HH + 255) / 256;
    const int fin_grid   = (NN + 7) / 8;

    for (int l = 0; l < LL; l++) {
        gemm128<<<gemm_grid, 256>>>(Wl + (size_t)l * DD * DD, 0, 1);
        gemm128<<<gemm_grid, 256>>>(Wr + (size_t)l * DD * DD, 1, 1);
        init_layer<<<init_grid, 256>>>(bias + l * DD);
        edge_logits<<<edge_grid, 256>>>(ei, att + l * HH * CC);
        edge_exp<<<exp_grid, 256>>>(ei);
        edge_aggregate<<<edge_grid, 256>>>(ei);
        finalize<<<fin_grid, 256>>>(gamma + l * DD, beta + l * DD,
                                    (l == LL - 1) ? out : nullptr);
    }
}

// round 2
// speedup vs baseline: 1.4420x; 1.4420x over previous
#include <cuda_runtime.h>
#include <cuda_bf16.h>
#include <math.h>

#define NN 50000
#define EE 800000
#define DD 128
#define HH 8
#define CC 16
#define LL 3
#define ET (EE + NN)   // 850000 edges incl. self-loops
#define SLOPE 0.2f
#define LN_EPS 1e-5f

// ---------------- scratch (static device globals; no allocation allowed) ----
__device__ float g_h[NN * DD];       // evolving node features
__device__ float g_xl[NN * DD];      // h @ Wl
__device__ float g_xr[NN * DD];      // h @ Wr
__device__ float g_out[NN * DD];     // segment-sum accumulator (+bias)
__device__ float g_denom[NN * HH];   // segment sum of exp
__device__ float g_ex[ET * HH];      // per-edge exp(logit)

// ---------------- helpers ---------------------------------------------------
__device__ __forceinline__ float lrelu(float x) {
    return x > 0.f ? x : SLOPE * x;
}

// ---------------- fused dual GEMM: xl = h@Wl, xr = h@Wr ---------------------
// Block 256 threads, tile 64 rows x 128 cols, each thread 4x8 outputs per matrix.
__global__ __launch_bounds__(256, 2) void gemm_dual(const float* __restrict__ Wl,
                                                    const float* __restrict__ Wr) {
    __shared__ float Xs[16][64];      // transposed: [k][row]
    __shared__ float Wls[16][128];
    __shared__ float Wrs[16][128];

    const float* __restrict__ X = g_h;
    int tid = threadIdx.x;
    int tx = tid & 15;    // col group (8 cols)
    int ty = tid >> 4;    // row group (4 rows)
    int row0 = blockIdx.x * 64;

    float accL[4][8], accR[4][8];
#pragma unroll
    for (int i = 0; i < 4; i++)
#pragma unroll
        for (int j = 0; j < 8; j++) { accL[i][j] = 0.f; accR[i][j] = 0.f; }

    // load indices
    int xr_row = tid & 63;            // 0..63
    int xr_kq  = tid >> 6;            // 0..3 (4 k's each)
    int w_c    = (tid & 31) * 4;      // 0..124
    int w_k    = tid >> 5;            // 0..7

    for (int k0 = 0; k0 < 128; k0 += 16) {
        {   // X tile: 64 rows x 16 k, stored transposed
            int gr = row0 + xr_row;
            float4 v = make_float4(0.f, 0.f, 0.f, 0.f);
            if (gr < NN) v = *(const float4*)(X + gr * 128 + k0 + xr_kq * 4);
            Xs[xr_kq * 4 + 0][xr_row] = v.x;
            Xs[xr_kq * 4 + 1][xr_row] = v.y;
            Xs[xr_kq * 4 + 2][xr_row] = v.z;
            Xs[xr_kq * 4 + 3][xr_row] = v.w;
        }
        {   // W tiles: 16 k x 128 c each
#pragma unroll
            for (int kk = 0; kk < 16; kk += 8) {
                int k = w_k + kk;
                *(float4*)(&Wls[k][w_c]) = *(const float4*)(Wl + (k0 + k) * 128 + w_c);
                *(float4*)(&Wrs[k][w_c]) = *(const float4*)(Wr + (k0 + k) * 128 + w_c);
            }
        }
        __syncthreads();
#pragma unroll
        for (int kk = 0; kk < 16; kk++) {
            float4 av = *(const float4*)(&Xs[kk][ty * 4]);
            float a[4] = {av.x, av.y, av.z, av.w};
            float4 b0 = *(const float4*)(&Wls[kk][tx * 8]);
            float4 b1 = *(const float4*)(&Wls[kk][tx * 8 + 4]);
            float4 c0 = *(const float4*)(&Wrs[kk][tx * 8]);
            float4 c1 = *(const float4*)(&Wrs[kk][tx * 8 + 4]);
            float bl[8] = {b0.x, b0.y, b0.z, b0.w, b1.x, b1.y, b1.z, b1.w};
            float br[8] = {c0.x, c0.y, c0.z, c0.w, c1.x, c1.y, c1.z, c1.w};
#pragma unroll
            for (int i = 0; i < 4; i++)
#pragma unroll
                for (int j = 0; j < 8; j++) {
                    accL[i][j] += a[i] * bl[j];
                    accR[i][j] += a[i] * br[j];
                }
        }
        __syncthreads();
    }

#pragma unroll
    for (int i = 0; i < 4; i++) {
        int gr = row0 + ty * 4 + i;
        if (gr < NN) {
            *(float4*)(g_xl + gr * 128 + tx * 8)     = make_float4(accL[i][0], accL[i][1], accL[i][2], accL[i][3]);
            *(float4*)(g_xl + gr * 128 + tx * 8 + 4) = make_float4(accL[i][4], accL[i][5], accL[i][6], accL[i][7]);
            *(float4*)(g_xr + gr * 128 + tx * 8)     = make_float4(accR[i][0], accR[i][1], accR[i][2], accR[i][3]);
            *(float4*)(g_xr + gr * 128 + tx * 8 + 4) = make_float4(accR[i][4], accR[i][5], accR[i][6], accR[i][7]);
        }
    }
}

// ---------------- per-layer init: out=bias, denom=0 -------------------------
__global__ void init_layer(const float* __restrict__ bias_l) {
    int i = blockIdx.x * blockDim.x + threadIdx.x;
    if (i < NN * DD) g_out[i] = bias_l[i & 127];
    if (i < NN * HH) g_denom[i] = 0.f;
}

// ---------------- pass A: logits -> exp -> segment denom --------------------
// one warp per edge; lane handles 4 channels; 4 lanes per head
// (no segment-max: logits are bounded, softmax is shift-invariant)
__global__ void edge_logits_exp(const int* __restrict__ ei,
                                const float* __restrict__ att_l) {
    int e = blockIdx.x * 8 + (threadIdx.x >> 5);
    if (e >= ET) return;
    int lane = threadIdx.x & 31;
    int src, dst;
    if (e < EE) { src = __ldg(ei + e); dst = __ldg(ei + EE + e); }
    else        { src = e - EE; dst = src; }

    int c0 = lane * 4;
    float4 a = *(const float4*)(g_xl + src * 128 + c0);
    float4 b = *(const float4*)(g_xr + dst * 128 + c0);
    float4 t = *(const float4*)(att_l + c0);

    float s = lrelu(a.x + b.x) * t.x + lrelu(a.y + b.y) * t.y +
              lrelu(a.z + b.z) * t.z + lrelu(a.w + b.w) * t.w;
    s += __shfl_xor_sync(0xffffffffu, s, 1);
    s += __shfl_xor_sync(0xffffffffu, s, 2);

    if ((lane & 3) == 0) {
        int h = lane >> 2;
        float v = __expf(s);
        g_ex[e * HH + h] = v;
        atomicAdd(&g_denom[dst * HH + h], v);
    }
}

// ---------------- pass B: alpha-weighted scatter-add (vector RED) -----------
__global__ void edge_aggregate(const int* __restrict__ ei) {
    int e = blockIdx.x * 8 + (threadIdx.x >> 5);
    if (e >= ET) return;
    int lane = threadIdx.x & 31;
    int src, dst;
    if (e < EE) { src = __ldg(ei + e); dst = __ldg(ei + EE + e); }
    else        { src = e - EE; dst = src; }

    int h = lane >> 2;
    float alpha = g_ex[e * HH + h] / g_denom[dst * HH + h];
    int c0 = lane * 4;
    float4 a = *(const float4*)(g_xl + src * 128 + c0);
    float* o = g_out + dst * 128 + c0;
    asm volatile("red.global.add.v4.f32 [%0], {%1, %2, %3, %4};"
                 :: "l"(o), "f"(alpha * a.x), "f"(alpha * a.y),
                    "f"(alpha * a.z), "f"(alpha * a.w)
                 : "memory");
}

// ---------------- LayerNorm + ELU + residual --------------------------------
__global__ void finalize(const float* __restrict__ gamma_l,
                         const float* __restrict__ beta_l,
                         float* __restrict__ final_out) {
    int n = blockIdx.x * (blockDim.x >> 5) + (threadIdx.x >> 5);
    if (n >= NN) return;
    int lane = threadIdx.x & 31;
    int c0 = lane * 4;

    float4 y = *(const float4*)(g_out + n * 128 + c0);
    float sum = y.x + y.y + y.z + y.w;
#pragma unroll
    for (int o = 16; o; o >>= 1) sum += __shfl_xor_sync(0xffffffffu, sum, o);
    float mu = sum * (1.f / 128.f);

    float dx = y.x - mu, dy = y.y - mu, dz = y.z - mu, dw = y.w - mu;
    float vs = dx * dx + dy * dy + dz * dz + dw * dw;
#pragma unroll
    for (int o = 16; o; o >>= 1) vs += __shfl_xor_sync(0xffffffffu, vs, o);
    float rstd = rsqrtf(vs * (1.f / 128.f) + LN_EPS);

    float4 g = *(const float4*)(gamma_l + c0);
    float4 bb = *(const float4*)(beta_l + c0);
    float4 hv = *(const float4*)(g_h + n * 128 + c0);

    float t;
    float4 r;
    t = dx * rstd * g.x + bb.x; r.x = hv.x + (t > 0.f ? t : expm1f(t));
    t = dy * rstd * g.y + bb.y; r.y = hv.y + (t > 0.f ? t : expm1f(t));
    t = dz * rstd * g.z + bb.z; r.z = hv.z + (t > 0.f ? t : expm1f(t));
    t = dw * rstd * g.w + bb.w; r.w = hv.w + (t > 0.f ? t : expm1f(t));

    *(float4*)(g_h + n * 128 + c0) = r;
    if (final_out) *(float4*)(final_out + n * 128 + c0) = r;
}

// ---------------- host orchestration ----------------------------------------
extern "C" void kernel_launch(void* const* d_in, const int* in_sizes, int n_in,
                              void* d_out, int out_size) {
    const float* x     = (const float*)d_in[0];
    const float* Wl    = (const float*)d_in[1];
    const float* Wr    = (const float*)d_in[2];
    const float* att   = (const float*)d_in[3];
    const float* bias  = (const float*)d_in[4];
    const float* gamma = (const float*)d_in[5];
    const float* beta  = (const float*)d_in[6];
    const int*   ei    = (const int*)d_in[7];
    float* out = (float*)d_out;

    void* h_ptr = nullptr;
    cudaGetSymbolAddress(&h_ptr, g_h);
    cudaMemcpyAsync(h_ptr, x, (size_t)NN * DD * sizeof(float),
                    cudaMemcpyDeviceToDevice);

    const int gemm_grid = (NN + 63) / 64;
    const int init_grid = (NN * DD + 255) / 256;
    const int edge_grid = (ET + 7) / 8;
    const int fin_grid  = (NN + 7) / 8;

    for (int l = 0; l < LL; l++) {
        gemm_dual<<<gemm_grid, 256>>>(Wl + (size_t)l * DD * DD,
                                      Wr + (size_t)l * DD * DD);
        init_layer<<<init_grid, 256>>>(bias + l * DD);
        edge_logits_exp<<<edge_grid, 256>>>(ei, att + l * HH * CC);
        edge_aggregate<<<edge_grid, 256>>>(ei);
        finalize<<<fin_grid, 256>>>(gamma + l * DD, beta + l * DD,
                                    (l == LL - 1) ? out : nullptr);
    }
}

// round 4
// speedup vs baseline: 2.1247x; 1.4735x over previous
#include <cuda_runtime.h>
#include <cuda_bf16.h>
#include <math.h>

#define NN 50000
#define EE 800000
#define DD 128
#define HH 8
#define CC 16
#define LL 3
#define ET (EE + NN)   // 850000 edges incl. self-loops
#define SLOPE 0.2f
#define LN_EPS 1e-5f

// ---------------- scratch (static device globals; no allocation allowed) ----
__device__ float g_h[NN * DD];       // evolving node features
__device__ float g_xl[NN * DD];      // h @ Wl
__device__ float g_xr[NN * DD];      // h @ Wr
__device__ float g_out[NN * DD];     // unnormalized message accumulator
__device__ float g_denom[NN * HH];   // segment sum of exp

// ---------------- helpers ---------------------------------------------------
__device__ __forceinline__ float lrelu(float x) {
    return x > 0.f ? x : SLOPE * x;
}

// ---------------- fused dual GEMM: xl = X@Wl, xr = X@Wr ---------------------
// Block 256 threads, tile 64 rows x 128 cols, each thread 4x8 outputs per matrix.
__global__ __launch_bounds__(256, 2) void gemm_dual(const float* __restrict__ X,
                                                    const float* __restrict__ Wl,
                                                    const float* __restrict__ Wr) {
    __shared__ float Xs[16][64];      // transposed: [k][row]
    __shared__ float Wls[16][128];
    __shared__ float Wrs[16][128];

    int tid = threadIdx.x;
    int tx = tid & 15;    // col group (8 cols)
    int ty = tid >> 4;    // row group (4 rows)
    int row0 = blockIdx.x * 64;

    float accL[4][8], accR[4][8];
#pragma unroll
    for (int i = 0; i < 4; i++)
#pragma unroll
        for (int j = 0; j < 8; j++) { accL[i][j] = 0.f; accR[i][j] = 0.f; }

    int xr_row = tid & 63;            // 0..63
    int xr_kq  = tid >> 6;            // 0..3 (4 k's each)
    int w_c    = (tid & 31) * 4;      // 0..124
    int w_k    = tid >> 5;            // 0..7

    for (int k0 = 0; k0 < 128; k0 += 16) {
        {   // X tile: 64 rows x 16 k, stored transposed
            int gr = row0 + xr_row;
            float4 v = make_float4(0.f, 0.f, 0.f, 0.f);
            if (gr < NN) v = *(const float4*)(X + gr * 128 + k0 + xr_kq * 4);
            Xs[xr_kq * 4 + 0][xr_row] = v.x;
            Xs[xr_kq * 4 + 1][xr_row] = v.y;
            Xs[xr_kq * 4 + 2][xr_row] = v.z;
            Xs[xr_kq * 4 + 3][xr_row] = v.w;
        }
        {   // W tiles: 16 k x 128 c each
#pragma unroll
            for (int kk = 0; kk < 16; kk += 8) {
                int k = w_k + kk;
                *(float4*)(&Wls[k][w_c]) = *(const float4*)(Wl + (k0 + k) * 128 + w_c);
                *(float4*)(&Wrs[k][w_c]) = *(const float4*)(Wr + (k0 + k) * 128 + w_c);
            }
        }
        __syncthreads();
#pragma unroll
        for (int kk = 0; kk < 16; kk++) {
            float4 av = *(const float4*)(&Xs[kk][ty * 4]);
            float a[4] = {av.x, av.y, av.z, av.w};
            float4 b0 = *(const float4*)(&Wls[kk][tx * 8]);
            float4 b1 = *(const float4*)(&Wls[kk][tx * 8 + 4]);
            float4 c0 = *(const float4*)(&Wrs[kk][tx * 8]);
            float4 c1 = *(const float4*)(&Wrs[kk][tx * 8 + 4]);
            float bl[8] = {b0.x, b0.y, b0.z, b0.w, b1.x, b1.y, b1.z, b1.w};
            float br[8] = {c0.x, c0.y, c0.z, c0.w, c1.x, c1.y, c1.z, c1.w};
#pragma unroll
            for (int i = 0; i < 4; i++)
#pragma unroll
                for (int j = 0; j < 8; j++) {
                    accL[i][j] += a[i] * bl[j];
                    accR[i][j] += a[i] * br[j];
                }
        }
        __syncthreads();
    }

#pragma unroll
    for (int i = 0; i < 4; i++) {
        int gr = row0 + ty * 4 + i;
        if (gr < NN) {
            *(float4*)(g_xl + gr * 128 + tx * 8)     = make_float4(accL[i][0], accL[i][1], accL[i][2], accL[i][3]);
            *(float4*)(g_xl + gr * 128 + tx * 8 + 4) = make_float4(accL[i][4], accL[i][5], accL[i][6], accL[i][7]);
            *(float4*)(g_xr + gr * 128 + tx * 8)     = make_float4(accR[i][0], accR[i][1], accR[i][2], accR[i][3]);
            *(float4*)(g_xr + gr * 128 + tx * 8 + 4) = make_float4(accR[i][4], accR[i][5], accR[i][6], accR[i][7]);
        }
    }
}

// ---------------- fused edge pass: logit -> exp -> scatter ------------------
// one warp per edge; lane handles 4 channels; 4 lanes per head.
// No segment-max (logits bounded, softmax shift-invariant).
// Denominator factored out: accumulate ex*xl, divide by denom in finalize.
__global__ void edge_fused(const int* __restrict__ ei,
                           const float* __restrict__ att_l) {
    int e = blockIdx.x * 8 + (threadIdx.x >> 5);
    if (e >= ET) return;
    int lane = threadIdx.x & 31;
    int src, dst;
    if (e < EE) { src = __ldg(ei + e); dst = __ldg(ei + EE + e); }
    else        { src = e - EE; dst = src; }

    int c0 = lane * 4;
    float4 a = *(const float4*)(g_xl + src * 128 + c0);
    float4 b = *(const float4*)(g_xr + dst * 128 + c0);
    float4 t = *(const float4*)(att_l + c0);

    float s = lrelu(a.x + b.x) * t.x + lrelu(a.y + b.y) * t.y +
              lrelu(a.z + b.z) * t.z + lrelu(a.w + b.w) * t.w;
    // xor-reduce within each 4-lane head group: all 4 lanes get full sum
    s += __shfl_xor_sync(0xffffffffu, s, 1);
    s += __shfl_xor_sync(0xffffffffu, s, 2);

    float v = __expf(s);

    float* o = g_out + dst * 128 + c0;
    asm volatile("red.global.add.v4.f32 [%0], {%1, %2, %3, %4};"
                 :: "l"(o), "f"(v * a.x), "f"(v * a.y),
                    "f"(v * a.z), "f"(v * a.w)
                 : "memory");

    if ((lane & 3) == 0) {
        atomicAdd(&g_denom[dst * HH + (lane >> 2)], v);
    }
}

// ---------------- finalize: /denom + bias -> LayerNorm -> ELU -> residual ---
__global__ void finalize(const float* __restrict__ bias_l,
                         const float* __restrict__ gamma_l,
                         const float* __restrict__ beta_l,
                         const float* __restrict__ resid,   // x for layer 0, g_h after
                         float* __restrict__ final_out) {
    int n = blockIdx.x * (blockDim.x >> 5) + (threadIdx.x >> 5);
    if (n >= NN) return;
    int lane = threadIdx.x & 31;
    int c0 = lane * 4;

    float inv_d = 1.f / g_denom[n * HH + (lane >> 2)];
    float4 y = *(const float4*)(g_out + n * 128 + c0);
    float4 bi = *(const float4*)(bias_l + c0);
    y.x = y.x * inv_d + bi.x;
    y.y = y.y * inv_d + bi.y;
    y.z = y.z * inv_d + bi.z;
    y.w = y.w * inv_d + bi.w;

    float sum = y.x + y.y + y.z + y.w;
#pragma unroll
    for (int o = 16; o; o >>= 1) sum += __shfl_xor_sync(0xffffffffu, sum, o);
    float mu = sum * (1.f / 128.f);

    float dx = y.x - mu, dy = y.y - mu, dz = y.z - mu, dw = y.w - mu;
    float vs = dx * dx + dy * dy + dz * dz + dw * dw;
#pragma unroll
    for (int o = 16; o; o >>= 1) vs += __shfl_xor_sync(0xffffffffu, vs, o);
    float rstd = rsqrtf(vs * (1.f / 128.f) + LN_EPS);

    float4 g = *(const float4*)(gamma_l + c0);
    float4 bb = *(const float4*)(beta_l + c0);
    float4 hv = *(const float4*)(resid + n * 128 + c0);

    float t;
    float4 r;
    t = dx * rstd * g.x + bb.x; r.x = hv.x + (t > 0.f ? t : expm1f(t));
    t = dy * rstd * g.y + bb.y; r.y = hv.y + (t > 0.f ? t : expm1f(t));
    t = dz * rstd * g.z + bb.z; r.z = hv.z + (t > 0.f ? t : expm1f(t));
    t = dw * rstd * g.w + bb.w; r.w = hv.w + (t > 0.f ? t : expm1f(t));

    *(float4*)(g_h + n * 128 + c0) = r;
    if (final_out) *(float4*)(final_out + n * 128 + c0) = r;
}

// ---------------- host orchestration ----------------------------------------
extern "C" void kernel_launch(void* const* d_in, const int* in_sizes, int n_in,
                              void* d_out, int out_size) {
    const float* x     = (const float*)d_in[0];
    const float* Wl    = (const float*)d_in[1];
    const float* Wr    = (const float*)d_in[2];
    const float* att   = (const float*)d_in[3];
    const float* bias  = (const float*)d_in[4];
    const float* gamma = (const float*)d_in[5];
    const float* beta  = (const float*)d_in[6];
    const int*   ei    = (const int*)d_in[7];
    float* out = (float*)d_out;

    void* out_ptr = nullptr;
    void* den_ptr = nullptr;
    void* h_ptr = nullptr;
    cudaGetSymbolAddress(&out_ptr, g_out);
    cudaGetSymbolAddress(&den_ptr, g_denom);
    cudaGetSymbolAddress(&h_ptr, g_h);

    const int gemm_grid = (NN + 63) / 64;
    const int edge_grid = (ET + 7) / 8;
    const int fin_grid  = (NN + 7) / 8;

    for (int l = 0; l < LL; l++) {
        const float* X = (l == 0) ? x : (const float*)h_ptr;
        gemm_dual<<<gemm_grid, 256>>>(X, Wl + (size_t)l * DD * DD,
                                      Wr + (size_t)l * DD * DD);
        cudaMemsetAsync(out_ptr, 0, (size_t)NN * DD * sizeof(float));
        cudaMemsetAsync(den_ptr, 0, (size_t)NN * HH * sizeof(float));
        edge_fused<<<edge_grid, 256>>>(ei, att + l * HH * CC);
        finalize<<<fin_grid, 256>>>(bias + l * DD, gamma + l * DD,
                                    beta + l * DD, X,
                                    (l == LL - 1) ? out : nullptr);
    }
}

// round 5
// speedup vs baseline: 2.6078x; 1.2273x over previous
#include <cuda_runtime.h>
#include <cuda_bf16.h>
#include <math.h>

#define NN 50000
#define EE 800000
#define DD 128
#define HH 8
#define CC 16
#define LL 3
#define SLOPE 0.2f
#define LN_EPS 1e-5f

// ---------------- scratch (static device globals; no allocation allowed) ----
__device__ float g_h[NN * DD];        // evolving node features
__device__ float g_xl[NN * DD];       // h @ Wl
__device__ float g_xr[NN * DD];       // h @ Wr
__device__ int   g_deg[NN];           // in-degree histogram
__device__ int   g_row[NN + 1];       // CSR row starts
__device__ int   g_cur[NN];           // fill cursors
__device__ int   g_csr[EE];           // src indices grouped by dst

// ---------------- helpers ---------------------------------------------------
__device__ __forceinline__ float lrelu(float x) {
    return x > 0.f ? x : SLOPE * x;
}

// ---------------- CSR build (once per launch) --------------------------------
__global__ void hist_kernel(const int* __restrict__ ei) {
    int e = blockIdx.x * blockDim.x + threadIdx.x;
    if (e < EE) atomicAdd(&g_deg[__ldg(ei + EE + e)], 1);
}

#define SCAN_THREADS 1024
#define SCAN_PER 49   // ceil(50000/1024)
__global__ void scan_kernel() {
    int tid = threadIdx.x;
    int start = tid * SCAN_PER;
    int end = start + SCAN_PER; if (end > NN) end = NN;
    int s = 0;
    for (int i = start; i < end; i++) s += g_deg[i];

    int lane = tid & 31, wid = tid >> 5;
    int incl = s;
#pragma unroll
    for (int o = 1; o < 32; o <<= 1) {
        int u = __shfl_up_sync(0xffffffffu, incl, o);
        if (lane >= o) incl += u;
    }
    __shared__ int wsum[32];
    if (lane == 31) wsum[wid] = incl;
    __syncthreads();
    if (wid == 0) {
        int w = wsum[lane];
#pragma unroll
        for (int o = 1; o < 32; o <<= 1) {
            int u = __shfl_up_sync(0xffffffffu, w, o);
            if (lane >= o) w += u;
        }
        wsum[lane] = w;
    }
    __syncthreads();
    int excl = incl - s + (wid > 0 ? wsum[wid - 1] : 0);

    int run = excl;
    for (int i = start; i < end; i++) {
        g_row[i] = run;
        g_cur[i] = run;
        run += g_deg[i];
    }
    if (tid == 0) g_row[NN] = EE;
}

__global__ void fill_kernel(const int* __restrict__ ei) {
    int e = blockIdx.x * blockDim.x + threadIdx.x;
    if (e < EE) {
        int dst = __ldg(ei + EE + e);
        int p = atomicAdd(&g_cur[dst], 1);
        g_csr[p] = __ldg(ei + e);
    }
}

// ---------------- fused dual GEMM: xl = X@Wl, xr = X@Wr ---------------------
__global__ __launch_bounds__(256, 2) void gemm_dual(const float* __restrict__ X,
                                                    const float* __restrict__ Wl,
                                                    const float* __restrict__ Wr) {
    __shared__ float Xs[16][64];      // transposed: [k][row]
    __shared__ float Wls[16][128];
    __shared__ float Wrs[16][128];

    int tid = threadIdx.x;
    int tx = tid & 15;
    int ty = tid >> 4;
    int row0 = blockIdx.x * 64;

    float accL[4][8], accR[4][8];
#pragma unroll
    for (int i = 0; i < 4; i++)
#pragma unroll
        for (int j = 0; j < 8; j++) { accL[i][j] = 0.f; accR[i][j] = 0.f; }

    int xr_row = tid & 63;
    int xr_kq  = tid >> 6;
    int w_c    = (tid & 31) * 4;
    int w_k    = tid >> 5;

    for (int k0 = 0; k0 < 128; k0 += 16) {
        {
            int gr = row0 + xr_row;
            float4 v = make_float4(0.f, 0.f, 0.f, 0.f);
            if (gr < NN) v = *(const float4*)(X + gr * 128 + k0 + xr_kq * 4);
            Xs[xr_kq * 4 + 0][xr_row] = v.x;
            Xs[xr_kq * 4 + 1][xr_row] = v.y;
            Xs[xr_kq * 4 + 2][xr_row] = v.z;
            Xs[xr_kq * 4 + 3][xr_row] = v.w;
        }
        {
#pragma unroll
            for (int kk = 0; kk < 16; kk += 8) {
                int k = w_k + kk;
                *(float4*)(&Wls[k][w_c]) = *(const float4*)(Wl + (k0 + k) * 128 + w_c);
                *(float4*)(&Wrs[k][w_c]) = *(const float4*)(Wr + (k0 + k) * 128 + w_c);
            }
        }
        __syncthreads();
#pragma unroll
        for (int kk = 0; kk < 16; kk++) {
            float4 av = *(const float4*)(&Xs[kk][ty * 4]);
            float a[4] = {av.x, av.y, av.z, av.w};
            float4 b0 = *(const float4*)(&Wls[kk][tx * 8]);
            float4 b1 = *(const float4*)(&Wls[kk][tx * 8 + 4]);
            float4 c0 = *(const float4*)(&Wrs[kk][tx * 8]);
            float4 c1 = *(const float4*)(&Wrs[kk][tx * 8 + 4]);
            float bl[8] = {b0.x, b0.y, b0.z, b0.w, b1.x, b1.y, b1.z, b1.w};
            float br[8] = {c0.x, c0.y, c0.z, c0.w, c1.x, c1.y, c1.z, c1.w};
#pragma unroll
            for (int i = 0; i < 4; i++)
#pragma unroll
                for (int j = 0; j < 8; j++) {
                    accL[i][j] += a[i] * bl[j];
                    accR[i][j] += a[i] * br[j];
                }
        }
        __syncthreads();
    }

#pragma unroll
    for (int i = 0; i < 4; i++) {
        int gr = row0 + ty * 4 + i;
        if (gr < NN) {
            *(float4*)(g_xl + gr * 128 + tx * 8)     = make_float4(accL[i][0], accL[i][1], accL[i][2], accL[i][3]);
            *(float4*)(g_xl + gr * 128 + tx * 8 + 4) = make_float4(accL[i][4], accL[i][5], accL[i][6], accL[i][7]);
            *(float4*)(g_xr + gr * 128 + tx * 8)     = make_float4(accR[i][0], accR[i][1], accR[i][2], accR[i][3]);
            *(float4*)(g_xr + gr * 128 + tx * 8 + 4) = make_float4(accR[i][4], accR[i][5], accR[i][6], accR[i][7]);
        }
    }
}

// ---------------- CSR edge pass + softmax + LN + ELU + residual -------------
// One warp per dst node. Lane owns 4 channels; 4 lanes per head.
// Denominator factored out of the edge sum; no segment-max (logits bounded).
__global__ __launch_bounds__(256) void edge_csr(const float* __restrict__ att_l,
                                                const float* __restrict__ bias_l,
                                                const float* __restrict__ gamma_l,
                                                const float* __restrict__ beta_l,
                                                const float* __restrict__ resid,
                                                float* __restrict__ final_out) {
    int n = blockIdx.x * 8 + (threadIdx.x >> 5);
    if (n >= NN) return;
    int lane = threadIdx.x & 31;
    int c0 = lane * 4;

    float4 xr = *(const float4*)(g_xr + n * 128 + c0);
    float4 t  = *(const float4*)(att_l + c0);

    // self-loop edge (src = dst = n)
    float4 a = *(const float4*)(g_xl + n * 128 + c0);
    float s = lrelu(a.x + xr.x) * t.x + lrelu(a.y + xr.y) * t.y +
              lrelu(a.z + xr.z) * t.z + lrelu(a.w + xr.w) * t.w;
    s += __shfl_xor_sync(0xffffffffu, s, 1);
    s += __shfl_xor_sync(0xffffffffu, s, 2);
    float v = __expf(s);
    float4 acc = make_float4(v * a.x, v * a.y, v * a.z, v * a.w);
    float denom = v;

    int i = g_row[n];
    int endi = g_row[n + 1];
    for (; i + 1 < endi; i += 2) {
        int s0 = __ldg(g_csr + i);
        int s1 = __ldg(g_csr + i + 1);
        float4 a0 = *(const float4*)(g_xl + s0 * 128 + c0);
        float4 a1 = *(const float4*)(g_xl + s1 * 128 + c0);
        float l0 = lrelu(a0.x + xr.x) * t.x + lrelu(a0.y + xr.y) * t.y +
                   lrelu(a0.z + xr.z) * t.z + lrelu(a0.w + xr.w) * t.w;
        float l1 = lrelu(a1.x + xr.x) * t.x + lrelu(a1.y + xr.y) * t.y +
                   lrelu(a1.z + xr.z) * t.z + lrelu(a1.w + xr.w) * t.w;
        l0 += __shfl_xor_sync(0xffffffffu, l0, 1);
        l0 += __shfl_xor_sync(0xffffffffu, l0, 2);
        l1 += __shfl_xor_sync(0xffffffffu, l1, 1);
        l1 += __shfl_xor_sync(0xffffffffu, l1, 2);
        float v0 = __expf(l0);
        float v1 = __expf(l1);
        acc.x += v0 * a0.x + v1 * a1.x;
        acc.y += v0 * a0.y + v1 * a1.y;
        acc.z += v0 * a0.z + v1 * a1.z;
        acc.w += v0 * a0.w + v1 * a1.w;
        denom += v0 + v1;
    }
    if (i < endi) {
        int s0 = __ldg(g_csr + i);
        float4 a0 = *(const float4*)(g_xl + s0 * 128 + c0);
        float l0 = lrelu(a0.x + xr.x) * t.x + lrelu(a0.y + xr.y) * t.y +
                   lrelu(a0.z + xr.z) * t.z + lrelu(a0.w + xr.w) * t.w;
        l0 += __shfl_xor_sync(0xffffffffu, l0, 1);
        l0 += __shfl_xor_sync(0xffffffffu, l0, 2);
        float v0 = __expf(l0);
        acc.x += v0 * a0.x;
        acc.y += v0 * a0.y;
        acc.z += v0 * a0.z;
        acc.w += v0 * a0.w;
        denom += v0;
    }

    // normalize + bias
    float inv_d = 1.f / denom;
    float4 bi = *(const float4*)(bias_l + c0);
    float4 y;
    y.x = acc.x * inv_d + bi.x;
    y.y = acc.y * inv_d + bi.y;
    y.z = acc.z * inv_d + bi.z;
    y.w = acc.w * inv_d + bi.w;

    // LayerNorm across the warp's 128 channels
    float sum = y.x + y.y + y.z + y.w;
#pragma unroll
    for (int o = 16; o; o >>= 1) sum += __shfl_xor_sync(0xffffffffu, sum, o);
    float mu = sum * (1.f / 128.f);

    float dx = y.x - mu, dy = y.y - mu, dz = y.z - mu, dw = y.w - mu;
    float vs = dx * dx + dy * dy + dz * dz + dw * dw;
#pragma unroll
    for (int o = 16; o; o >>= 1) vs += __shfl_xor_sync(0xffffffffu, vs, o);
    float rstd = rsqrtf(vs * (1.f / 128.f) + LN_EPS);

    float4 g  = *(const float4*)(gamma_l + c0);
    float4 bb = *(const float4*)(beta_l + c0);
    float4 hv = *(const float4*)(resid + n * 128 + c0);

    float tt;
    float4 r;
    tt = dx * rstd * g.x + bb.x; r.x = hv.x + (tt > 0.f ? tt : expm1f(tt));
    tt = dy * rstd * g.y + bb.y; r.y = hv.y + (tt > 0.f ? tt : expm1f(tt));
    tt = dz * rstd * g.z + bb.z; r.z = hv.z + (tt > 0.f ? tt : expm1f(tt));
    tt = dw * rstd * g.w + bb.w; r.w = hv.w + (tt > 0.f ? tt : expm1f(tt));

    *(float4*)(g_h + n * 128 + c0) = r;
    if (final_out) *(float4*)(final_out + n * 128 + c0) = r;
}

// ---------------- host orchestration ----------------------------------------
extern "C" void kernel_launch(void* const* d_in, const int* in_sizes, int n_in,
                              void* d_out, int out_size) {
    const float* x     = (const float*)d_in[0];
    const float* Wl    = (const float*)d_in[1];
    const float* Wr    = (const float*)d_in[2];
    const float* att   = (const float*)d_in[3];
    const float* bias  = (const float*)d_in[4];
    const float* gamma = (const float*)d_in[5];
    const float* beta  = (const float*)d_in[6];
    const int*   ei    = (const int*)d_in[7];
    float* out = (float*)d_out;

    void* deg_ptr = nullptr;
    void* h_ptr = nullptr;
    cudaGetSymbolAddress(&deg_ptr, g_deg);
    cudaGetSymbolAddress(&h_ptr, g_h);

    // build CSR (dst -> list of src), once per launch
    cudaMemsetAsync(deg_ptr, 0, NN * sizeof(int));
    hist_kernel<<<(EE + 255) / 256, 256>>>(ei);
    scan_kernel<<<1, SCAN_THREADS>>>();
    fill_kernel<<<(EE + 255) / 256, 256>>>(ei);

    const int gemm_grid = (NN + 63) / 64;
    const int node_grid = (NN + 7) / 8;

    for (int l = 0; l < LL; l++) {
        const float* X = (l == 0) ? x : (const float*)h_ptr;
        gemm_dual<<<gemm_grid, 256>>>(X, Wl + (size_t)l * DD * DD,
                                      Wr + (size_t)l * DD * DD);
        edge_csr<<<node_grid, 256>>>(att + l * HH * CC, bias + l * DD,
                                     gamma + l * DD, beta + l * DD, X,
                                     (l == LL - 1) ? out : nullptr);
    }
}

// round 7
// speedup vs baseline: 3.1133x; 1.1938x over previous
#include <cuda_runtime.h>
#include <cuda_bf16.h>
#include <math.h>
#include <stdint.h>

#define NN 50000
#define EE 800000
#define DD 128
#define HH 8
#define LL 3
#define SLOPE 0.2f
#define LN_EPS 1e-5f

// ---------------- scratch (static device globals; no allocation allowed) ----
__device__ float g_h[NN * DD];        // evolving node features
__device__ float g_xl[NN * DD];       // h @ Wl
__device__ float g_xr[NN * DD];       // h @ Wr
__device__ int   g_deg[NN];
__device__ int   g_row[NN + 1];
__device__ int   g_cur[NN];
__device__ int   g_csr[EE];

// ---------------- helpers ---------------------------------------------------
__device__ __forceinline__ float lrelu(float x) { return x > 0.f ? x : SLOPE * x; }

// packed dual-fp32 FMA (Blackwell FFMA2; only reachable via PTX)
#define FMA_F32X2(d, a, b, c) \
    asm("fma.rn.f32x2 %0, %1, %2, %3;" : "=l"(d) : "l"(a), "l"(b), "l"(c))
#define PACK_DUP_F32X2(out, v) \
    asm("mov.b64 %0, {%1, %1};" : "=l"(out) : "f"(v))
#define UNPACK_F32X2(lo, hi, in) \
    asm("mov.b64 {%0, %1}, %2;" : "=f"(lo), "=f"(hi) : "l"(in))

// ---------------- CSR build (once per launch) --------------------------------
__global__ void hist_kernel(const int* __restrict__ ei) {
    int e = blockIdx.x * blockDim.x + threadIdx.x;
    if (e < EE) atomicAdd(&g_deg[__ldg(ei + EE + e)], 1);
}

#define SCAN_THREADS 1024
#define SCAN_PER 49
__global__ void scan_kernel() {
    int tid = threadIdx.x;
    int start = tid * SCAN_PER;
    int end = start + SCAN_PER; if (end > NN) end = NN;
    int s = 0;
    for (int i = start; i < end; i++) s += g_deg[i];

    int lane = tid & 31, wid = tid >> 5;
    int incl = s;
#pragma unroll
    for (int o = 1; o < 32; o <<= 1) {
        int u = __shfl_up_sync(0xffffffffu, incl, o);
        if (lane >= o) incl += u;
    }
    __shared__ int wsum[32];
    if (lane == 31) wsum[wid] = incl;
    __syncthreads();
    if (wid == 0) {
        int w = wsum[lane];
#pragma unroll
        for (int o = 1; o < 32; o <<= 1) {
            int u = __shfl_up_sync(0xffffffffu, w, o);
            if (lane >= o) w += u;
        }
        wsum[lane] = w;
    }
    __syncthreads();
    int excl = incl - s + (wid > 0 ? wsum[wid - 1] : 0);
    int run = excl;
    for (int i = start; i < end; i++) {
        g_row[i] = run;
        g_cur[i] = run;
        run += g_deg[i];
    }
    if (tid == 0) g_row[NN] = EE;
}

__global__ void fill_kernel(const int* __restrict__ ei) {
    int e = blockIdx.x * blockDim.x + threadIdx.x;
    if (e < EE) {
        int dst = __ldg(ei + EE + e);
        int p = atomicAdd(&g_cur[dst], 1);
        g_csr[p] = __ldg(ei + e);
    }
}

// ---------------- fused dual GEMM via packed f32x2 FMA ----------------------
// Block 256 threads, tile 128 rows x (128+128) cols, 8x8 per thread per matrix.
__global__ __launch_bounds__(256, 1) void gemm_dual(const float* __restrict__ X,
                                                    const float* __restrict__ Wl,
                                                    const float* __restrict__ Wr) {
    __shared__ float Xs[16][128];     // transposed: [k][row]
    __shared__ float Wls[16][128];
    __shared__ float Wrs[16][128];

    int tid = threadIdx.x;
    int tx = tid & 15;    // col group: 8 cols = 4 f32x2 pairs
    int ty = tid >> 4;    // row group: 8 rows
    int row0 = blockIdx.x * 128;

    // accumulators: [row][colpair], packed two adjacent columns
    unsigned long long accL[8][4], accR[8][4];
#pragma unroll
    for (int i = 0; i < 8; i++)
#pragma unroll
        for (int j = 0; j < 4; j++) { accL[i][j] = 0ull; accR[i][j] = 0ull; }

    int xr_row = tid & 127;           // 0..127
    int xr_kq  = tid >> 7;            // 0..1 (8 k's each)
    int w_c    = (tid & 31) * 4;      // 0..124
    int w_k    = tid >> 5;            // 0..7

    for (int k0 = 0; k0 < 128; k0 += 16) {
        {   // X tile: 128 rows x 16 k, stored transposed
            int gr = row0 + xr_row;
#pragma unroll
            for (int q = 0; q < 2; q++) {
                int kk = xr_kq * 8 + q * 4;
                float4 v = make_float4(0.f, 0.f, 0.f, 0.f);
                if (gr < NN) v = *(const float4*)(X + (size_t)gr * 128 + k0 + kk);
                Xs[kk + 0][xr_row] = v.x;
                Xs[kk + 1][xr_row] = v.y;
                Xs[kk + 2][xr_row] = v.z;
                Xs[kk + 3][xr_row] = v.w;
            }
        }
        {   // W tiles: 16 k x 128 c each
#pragma unroll
            for (int kk = 0; kk < 16; kk += 8) {
                int k = w_k + kk;
                *(float4*)(&Wls[k][w_c]) = *(const float4*)(Wl + (size_t)(k0 + k) * 128 + w_c);
                *(float4*)(&Wrs[k][w_c]) = *(const float4*)(Wr + (size_t)(k0 + k) * 128 + w_c);
            }
        }
        __syncthreads();
#pragma unroll
        for (int kk = 0; kk < 16; kk++) {
            // A: 8 rows
            float4 a0 = *(const float4*)(&Xs[kk][ty * 8]);
            float4 a1 = *(const float4*)(&Xs[kk][ty * 8 + 4]);
            float a[8] = {a0.x, a0.y, a0.z, a0.w, a1.x, a1.y, a1.z, a1.w};
            // B: 4 col-pairs per matrix
            ulonglong2 bl0 = *(const ulonglong2*)(&Wls[kk][tx * 8]);
            ulonglong2 bl1 = *(const ulonglong2*)(&Wls[kk][tx * 8 + 4]);
            ulonglong2 br0 = *(const ulonglong2*)(&Wrs[kk][tx * 8]);
            ulonglong2 br1 = *(const ulonglong2*)(&Wrs[kk][tx * 8 + 4]);
            unsigned long long bl[4] = {bl0.x, bl0.y, bl1.x, bl1.y};
            unsigned long long br[4] = {br0.x, br0.y, br1.x, br1.y};
#pragma unroll
            for (int i = 0; i < 8; i++) {
                unsigned long long aa;
                PACK_DUP_F32X2(aa, a[i]);
#pragma unroll
                for (int j = 0; j < 4; j++) {
                    FMA_F32X2(accL[i][j], aa, bl[j], accL[i][j]);
                    FMA_F32X2(accR[i][j], aa, br[j], accR[i][j]);
                }
            }
        }
        __syncthreads();
    }

#pragma unroll
    for (int i = 0; i < 8; i++) {
        int gr = row0 + ty * 8 + i;
        if (gr < NN) {
            float f[8];
#pragma unroll
            for (int j = 0; j < 4; j++) UNPACK_F32X2(f[j * 2], f[j * 2 + 1], accL[i][j]);
            *(float4*)(g_xl + (size_t)gr * 128 + tx * 8)     = make_float4(f[0], f[1], f[2], f[3]);
            *(float4*)(g_xl + (size_t)gr * 128 + tx * 8 + 4) = make_float4(f[4], f[5], f[6], f[7]);
#pragma unroll
            for (int j = 0; j < 4; j++) UNPACK_F32X2(f[j * 2], f[j * 2 + 1], accR[i][j]);
            *(float4*)(g_xr + (size_t)gr * 128 + tx * 8)     = make_float4(f[0], f[1], f[2], f[3]);
            *(float4*)(g_xr + (size_t)gr * 128 + tx * 8 + 4) = make_float4(f[4], f[5], f[6], f[7]);
        }
    }
}

// ---------------- CSR edge pass + softmax + LN + ELU + residual -------------
__global__ __launch_bounds__(256) void edge_csr(const float* __restrict__ att_l,
                                                const float* __restrict__ bias_l,
                                                const float* __restrict__ gamma_l,
                                                const float* __restrict__ beta_l,
                                                const float* __restrict__ resid,
                                                float* __restrict__ final_out) {
    int n = blockIdx.x * 8 + (threadIdx.x >> 5);
    if (n >= NN) return;
    int lane = threadIdx.x & 31;
    int c0 = lane * 4;

    float4 xr = *(const float4*)(g_xr + (size_t)n * 128 + c0);
    float4 t  = *(const float4*)(att_l + c0);

    // self-loop
    float4 a = *(const float4*)(g_xl + (size_t)n * 128 + c0);
    float s = lrelu(a.x + xr.x) * t.x + lrelu(a.y + xr.y) * t.y +
              lrelu(a.z + xr.z) * t.z + lrelu(a.w + xr.w) * t.w;
    s += __shfl_xor_sync(0xffffffffu, s, 1);
    s += __shfl_xor_sync(0xffffffffu, s, 2);
    float v = __expf(s);
    float4 acc = make_float4(v * a.x, v * a.y, v * a.z, v * a.w);
    float denom = v;

    int i = g_row[n];
    int endi = g_row[n + 1];
    for (; i + 1 < endi; i += 2) {
        int s0 = __ldg(g_csr + i);
        int s1 = __ldg(g_csr + i + 1);
        float4 a0 = *(const float4*)(g_xl + (size_t)s0 * 128 + c0);
        float4 a1 = *(const float4*)(g_xl + (size_t)s1 * 128 + c0);
        float l0 = lrelu(a0.x + xr.x) * t.x + lrelu(a0.y + xr.y) * t.y +
                   lrelu(a0.z + xr.z) * t.z + lrelu(a0.w + xr.w) * t.w;
        float l1 = lrelu(a1.x + xr.x) * t.x + lrelu(a1.y + xr.y) * t.y +
                   lrelu(a1.z + xr.z) * t.z + lrelu(a1.w + xr.w) * t.w;
        l0 += __shfl_xor_sync(0xffffffffu, l0, 1);
        l0 += __shfl_xor_sync(0xffffffffu, l0, 2);
        l1 += __shfl_xor_sync(0xffffffffu, l1, 1);
        l1 += __shfl_xor_sync(0xffffffffu, l1, 2);
        float v0 = __expf(l0);
        float v1 = __expf(l1);
        acc.x += v0 * a0.x + v1 * a1.x;
        acc.y += v0 * a0.y + v1 * a1.y;
        acc.z += v0 * a0.z + v1 * a1.z;
        acc.w += v0 * a0.w + v1 * a1.w;
        denom += v0 + v1;
    }
    if (i < endi) {
        int s0 = __ldg(g_csr + i);
        float4 a0 = *(const float4*)(g_xl + (size_t)s0 * 128 + c0);
        float l0 = lrelu(a0.x + xr.x) * t.x + lrelu(a0.y + xr.y) * t.y +
                   lrelu(a0.z + xr.z) * t.z + lrelu(a0.w + xr.w) * t.w;
        l0 += __shfl_xor_sync(0xffffffffu, l0, 1);
        l0 += __shfl_xor_sync(0xffffffffu, l0, 2);
        float v0 = __expf(l0);
        acc.x += v0 * a0.x;
        acc.y += v0 * a0.y;
        acc.z += v0 * a0.z;
        acc.w += v0 * a0.w;
        denom += v0;
    }

    float inv_d = 1.f / denom;
    float4 bi = *(const float4*)(bias_l + c0);
    float4 y;
    y.x = acc.x * inv_d + bi.x;
    y.y = acc.y * inv_d + bi.y;
    y.z = acc.z * inv_d + bi.z;
    y.w = acc.w * inv_d + bi.w;

    float sum = y.x + y.y + y.z + y.w;
#pragma unroll
    for (int o = 16; o; o >>= 1) sum += __shfl_xor_sync(0xffffffffu, sum, o);
    float mu = sum * (1.f / 128.f);

    float dx = y.x - mu, dy = y.y - mu, dz = y.z - mu, dw = y.w - mu;
    float vs = dx * dx + dy * dy + dz * dz + dw * dw;
#pragma unroll
    for (int o = 16; o; o >>= 1) vs += __shfl_xor_sync(0xffffffffu, vs, o);
    float rstd = rsqrtf(vs * (1.f / 128.f) + LN_EPS);

    float4 g  = *(const float4*)(gamma_l + c0);
    float4 bb = *(const float4*)(beta_l + c0);
    float4 hv = *(const float4*)(resid + (size_t)n * 128 + c0);

    float tt;
    float4 r;
    tt = dx * rstd * g.x + bb.x; r.x = hv.x + (tt > 0.f ? tt : expm1f(tt));
    tt = dy * rstd * g.y + bb.y; r.y = hv.y + (tt > 0.f ? tt : expm1f(tt));
    tt = dz * rstd * g.z + bb.z; r.z = hv.z + (tt > 0.f ? tt : expm1f(tt));
    tt = dw * rstd * g.w + bb.w; r.w = hv.w + (tt > 0.f ? tt : expm1f(tt));

    *(float4*)(g_h + (size_t)n * 128 + c0) = r;
    if (final_out) *(float4*)(final_out + (size_t)n * 128 + c0) = r;
}

// ---------------- host orchestration ----------------------------------------
extern "C" void kernel_launch(void* const* d_in, const int* in_sizes, int n_in,
                              void* d_out, int out_size) {
    const float* x     = (const float*)d_in[0];
    const float* Wl    = (const float*)d_in[1];
    const float* Wr    = (const float*)d_in[2];
    const float* att   = (const float*)d_in[3];
    const float* bias  = (const float*)d_in[4];
    const float* gamma = (const float*)d_in[5];
    const float* beta  = (const float*)d_in[6];
    const int*   ei    = (const int*)d_in[7];
    float* out = (float*)d_out;

    void* deg_ptr = nullptr;
    void* h_ptr = nullptr;
    cudaGetSymbolAddress(&deg_ptr, g_deg);
    cudaGetSymbolAddress(&h_ptr, g_h);

    // build CSR (dst -> list of src), once per launch
    cudaMemsetAsync(deg_ptr, 0, NN * sizeof(int));
    hist_kernel<<<(EE + 255) / 256, 256>>>(ei);
    scan_kernel<<<1, SCAN_THREADS>>>();
    fill_kernel<<<(EE + 255) / 256, 256>>>(ei);

    const int gemm_grid = (NN + 127) / 128;   // 391
    const int node_grid = (NN + 7) / 8;

    for (int l = 0; l < LL; l++) {
        const float* X = (l == 0) ? x : (const float*)h_ptr;
        gemm_dual<<<gemm_grid, 256>>>(X, Wl + (size_t)l * DD * DD,
                                      Wr + (size_t)l * DD * DD);
        edge_csr<<<node_grid, 256>>>(att + l * HH * 16, bias + l * DD,
                                     gamma + l * DD, beta + l * DD, X,
                                     (l == LL - 1) ? out : nullptr);
    }
}

// round 8
// speedup vs baseline: 3.1175x; 1.0014x over previous
#include <cuda_runtime.h>
#include <cuda_bf16.h>
#include <math.h>
#include <stdint.h>

#define NN 50000
#define EE 800000
#define DD 128
#define HH 8
#define LL 3
#define SLOPE 0.2f
#define LN_EPS 1e-5f

// ---------------- scratch (static device globals; no allocation allowed) ----
__device__ float g_h[NN * DD];        // evolving node features
__device__ float g_xl[NN * DD];       // h @ Wl
__device__ float g_xr[NN * DD];       // h @ Wr
__device__ int   g_deg[NN];
__device__ int   g_row[NN + 1];
__device__ int   g_cur[NN];
__device__ int   g_csr[EE];

// ---------------- helpers ---------------------------------------------------
__device__ __forceinline__ float lrelu(float x) { return x > 0.f ? x : SLOPE * x; }

// packed dual-fp32 FMA (Blackwell FFMA2; only reachable via PTX)
#define FMA_F32X2(d, a, b, c) \
    asm("fma.rn.f32x2 %0, %1, %2, %3;" : "=l"(d) : "l"(a), "l"(b), "l"(c))
#define PACK_DUP_F32X2(out, v) \
    asm("mov.b64 %0, {%1, %1};" : "=l"(out) : "f"(v))
#define UNPACK_F32X2(lo, hi, in) \
    asm("mov.b64 {%0, %1}, %2;" : "=f"(lo), "=f"(hi) : "l"(in))

// ---------------- CSR build (once per launch) --------------------------------
__global__ void hist_kernel(const int* __restrict__ ei) {
    int e = blockIdx.x * blockDim.x + threadIdx.x;
    if (e < EE) atomicAdd(&g_deg[__ldg(ei + EE + e)], 1);
}

#define SCAN_THREADS 1024
#define SCAN_PER 49
__global__ void scan_kernel() {
    int tid = threadIdx.x;
    int start = tid * SCAN_PER;
    int end = start + SCAN_PER; if (end > NN) end = NN;
    int s = 0;
    for (int i = start; i < end; i++) s += g_deg[i];

    int lane = tid & 31, wid = tid >> 5;
    int incl = s;
#pragma unroll
    for (int o = 1; o < 32; o <<= 1) {
        int u = __shfl_up_sync(0xffffffffu, incl, o);
        if (lane >= o) incl += u;
    }
    __shared__ int wsum[32];
    if (lane == 31) wsum[wid] = incl;
    __syncthreads();
    if (wid == 0) {
        int w = wsum[lane];
#pragma unroll
        for (int o = 1; o < 32; o <<= 1) {
            int u = __shfl_up_sync(0xffffffffu, w, o);
            if (lane >= o) w += u;
        }
        wsum[lane] = w;
    }
    __syncthreads();
    int excl = incl - s + (wid > 0 ? wsum[wid - 1] : 0);
    int run = excl;
    for (int i = start; i < end; i++) {
        g_row[i] = run;
        g_cur[i] = run;
        run += g_deg[i];
    }
    if (tid == 0) g_row[NN] = EE;
}

__global__ void fill_kernel(const int* __restrict__ ei) {
    int e = blockIdx.x * blockDim.x + threadIdx.x;
    if (e < EE) {
        int dst = __ldg(ei + EE + e);
        int p = atomicAdd(&g_cur[dst], 1);
        g_csr[p] = __ldg(ei + e);
    }
}

// ---------------- fused dual GEMM via packed f32x2 FMA ----------------------
// Block 256 threads, tile 128 rows x (128+128) cols, 8x8 per thread per matrix.
__global__ __launch_bounds__(256, 1) void gemm_dual(const float* __restrict__ X,
                                                    const float* __restrict__ Wl,
                                                    const float* __restrict__ Wr) {
    __shared__ float Xs[16][128];     // transposed: [k][row]
    __shared__ float Wls[16][128];
    __shared__ float Wrs[16][128];

    int tid = threadIdx.x;
    int tx = tid & 15;    // col group: 8 cols = 4 f32x2 pairs
    int ty = tid >> 4;    // row group: 8 rows
    int row0 = blockIdx.x * 128;

    // accumulators: [row][colpair], packed two adjacent columns
    unsigned long long accL[8][4], accR[8][4];
#pragma unroll
    for (int i = 0; i < 8; i++)
#pragma unroll
        for (int j = 0; j < 4; j++) { accL[i][j] = 0ull; accR[i][j] = 0ull; }

    int xr_row = tid & 127;           // 0..127
    int xr_kq  = tid >> 7;            // 0..1 (8 k's each)
    int w_c    = (tid & 31) * 4;      // 0..124
    int w_k    = tid >> 5;            // 0..7

    for (int k0 = 0; k0 < 128; k0 += 16) {
        {   // X tile: 128 rows x 16 k, stored transposed
            int gr = row0 + xr_row;
#pragma unroll
            for (int q = 0; q < 2; q++) {
                int kk = xr_kq * 8 + q * 4;
                float4 v = make_float4(0.f, 0.f, 0.f, 0.f);
                if (gr < NN) v = *(const float4*)(X + (size_t)gr * 128 + k0 + kk);
                Xs[kk + 0][xr_row] = v.x;
                Xs[kk + 1][xr_row] = v.y;
                Xs[kk + 2][xr_row] = v.z;
                Xs[kk + 3][xr_row] = v.w;
            }
        }
        {   // W tiles: 16 k x 128 c each
#pragma unroll
            for (int kk = 0; kk < 16; kk += 8) {
                int k = w_k + kk;
                *(float4*)(&Wls[k][w_c]) = *(const float4*)(Wl + (size_t)(k0 + k) * 128 + w_c);
                *(float4*)(&Wrs[k][w_c]) = *(const float4*)(Wr + (size_t)(k0 + k) * 128 + w_c);
            }
        }
        __syncthreads();
#pragma unroll
        for (int kk = 0; kk < 16; kk++) {
            // A: 8 rows
            float4 a0 = *(const float4*)(&Xs[kk][ty * 8]);
            float4 a1 = *(const float4*)(&Xs[kk][ty * 8 + 4]);
            float a[8] = {a0.x, a0.y, a0.z, a0.w, a1.x, a1.y, a1.z, a1.w};
            // B: 4 col-pairs per matrix
            ulonglong2 bl0 = *(const ulonglong2*)(&Wls[kk][tx * 8]);
            ulonglong2 bl1 = *(const ulonglong2*)(&Wls[kk][tx * 8 + 4]);
            ulonglong2 br0 = *(const ulonglong2*)(&Wrs[kk][tx * 8]);
            ulonglong2 br1 = *(const ulonglong2*)(&Wrs[kk][tx * 8 + 4]);
            unsigned long long bl[4] = {bl0.x, bl0.y, bl1.x, bl1.y};
            unsigned long long br[4] = {br0.x, br0.y, br1.x, br1.y};
#pragma unroll
            for (int i = 0; i < 8; i++) {
                unsigned long long aa;
                PACK_DUP_F32X2(aa, a[i]);
#pragma unroll
                for (int j = 0; j < 4; j++) {
                    FMA_F32X2(accL[i][j], aa, bl[j], accL[i][j]);
                    FMA_F32X2(accR[i][j], aa, br[j], accR[i][j]);
                }
            }
        }
        __syncthreads();
    }

#pragma unroll
    for (int i = 0; i < 8; i++) {
        int gr = row0 + ty * 8 + i;
        if (gr < NN) {
            float f[8];
#pragma unroll
            for (int j = 0; j < 4; j++) UNPACK_F32X2(f[j * 2], f[j * 2 + 1], accL[i][j]);
            *(float4*)(g_xl + (size_t)gr * 128 + tx * 8)     = make_float4(f[0], f[1], f[2], f[3]);
            *(float4*)(g_xl + (size_t)gr * 128 + tx * 8 + 4) = make_float4(f[4], f[5], f[6], f[7]);
#pragma unroll
            for (int j = 0; j < 4; j++) UNPACK_F32X2(f[j * 2], f[j * 2 + 1], accR[i][j]);
            *(float4*)(g_xr + (size_t)gr * 128 + tx * 8)     = make_float4(f[0], f[1], f[2], f[3]);
            *(float4*)(g_xr + (size_t)gr * 128 + tx * 8 + 4) = make_float4(f[4], f[5], f[6], f[7]);
        }
    }
}

// ---------------- CSR edge pass + softmax + LN + ELU + residual -------------
__global__ __launch_bounds__(256) void edge_csr(const float* __restrict__ att_l,
                                                const float* __restrict__ bias_l,
                                                const float* __restrict__ gamma_l,
                                                const float* __restrict__ beta_l,
                                                const float* __restrict__ resid,
                                                float* __restrict__ final_out) {
    int n = blockIdx.x * 8 + (threadIdx.x >> 5);
    if (n >= NN) return;
    int lane = threadIdx.x & 31;
    int c0 = lane * 4;

    float4 xr = *(const float4*)(g_xr + (size_t)n * 128 + c0);
    float4 t  = *(const float4*)(att_l + c0);

    // self-loop
    float4 a = *(const float4*)(g_xl + (size_t)n * 128 + c0);
    float s = lrelu(a.x + xr.x) * t.x + lrelu(a.y + xr.y) * t.y +
              lrelu(a.z + xr.z) * t.z + lrelu(a.w + xr.w) * t.w;
    s += __shfl_xor_sync(0xffffffffu, s, 1);
    s += __shfl_xor_sync(0xffffffffu, s, 2);
    float v = __expf(s);
    float4 acc = make_float4(v * a.x, v * a.y, v * a.z, v * a.w);
    float denom = v;

    int i = g_row[n];
    int endi = g_row[n + 1];
    for (; i + 1 < endi; i += 2) {
        int s0 = __ldg(g_csr + i);
        int s1 = __ldg(g_csr + i + 1);
        float4 a0 = *(const float4*)(g_xl + (size_t)s0 * 128 + c0);
        float4 a1 = *(const float4*)(g_xl + (size_t)s1 * 128 + c0);
        float l0 = lrelu(a0.x + xr.x) * t.x + lrelu(a0.y + xr.y) * t.y +
                   lrelu(a0.z + xr.z) * t.z + lrelu(a0.w + xr.w) * t.w;
        float l1 = lrelu(a1.x + xr.x) * t.x + lrelu(a1.y + xr.y) * t.y +
                   lrelu(a1.z + xr.z) * t.z + lrelu(a1.w + xr.w) * t.w;
        l0 += __shfl_xor_sync(0xffffffffu, l0, 1);
        l0 += __shfl_xor_sync(0xffffffffu, l0, 2);
        l1 += __shfl_xor_sync(0xffffffffu, l1, 1);
        l1 += __shfl_xor_sync(0xffffffffu, l1, 2);
        float v0 = __expf(l0);
        float v1 = __expf(l1);
        acc.x += v0 * a0.x + v1 * a1.x;
        acc.y += v0 * a0.y + v1 * a1.y;
        acc.z += v0 * a0.z + v1 * a1.z;
        acc.w += v0 * a0.w + v1 * a1.w;
        denom += v0 + v1;
    }
    if (i < endi) {
        int s0 = __ldg(g_csr + i);
        float4 a0 = *(const float4*)(g_xl + (size_t)s0 * 128 + c0);
        float l0 = lrelu(a0.x + xr.x) * t.x + lrelu(a0.y + xr.y) * t.y +
                   lrelu(a0.z + xr.z) * t.z + lrelu(a0.w + xr.w) * t.w;
        l0 += __shfl_xor_sync(0xffffffffu, l0, 1);
        l0 += __shfl_xor_sync(0xffffffffu, l0, 2);
        float v0 = __expf(l0);
        acc.x += v0 * a0.x;
        acc.y += v0 * a0.y;
        acc.z += v0 * a0.z;
        acc.w += v0 * a0.w;
        denom += v0;
    }

    float inv_d = 1.f / denom;
    float4 bi = *(const float4*)(bias_l + c0);
    float4 y;
    y.x = acc.x * inv_d + bi.x;
    y.y = acc.y * inv_d + bi.y;
    y.z = acc.z * inv_d + bi.z;
    y.w = acc.w * inv_d + bi.w;

    float sum = y.x + y.y + y.z + y.w;
#pragma unroll
    for (int o = 16; o; o >>= 1) sum += __shfl_xor_sync(0xffffffffu, sum, o);
    float mu = sum * (1.f / 128.f);

    float dx = y.x - mu, dy = y.y - mu, dz = y.z - mu, dw = y.w - mu;
    float vs = dx * dx + dy * dy + dz * dz + dw * dw;
#pragma unroll
    for (int o = 16; o; o >>= 1) vs += __shfl_xor_sync(0xffffffffu, vs, o);
    float rstd = rsqrtf(vs * (1.f / 128.f) + LN_EPS);

    float4 g  = *(const float4*)(gamma_l + c0);
    float4 bb = *(const float4*)(beta_l + c0);
    float4 hv = *(const float4*)(resid + (size_t)n * 128 + c0);

    float tt;
    float4 r;
    tt = dx * rstd * g.x + bb.x; r.x = hv.x + (tt > 0.f ? tt : expm1f(tt));
    tt = dy * rstd * g.y + bb.y; r.y = hv.y + (tt > 0.f ? tt : expm1f(tt));
    tt = dz * rstd * g.z + bb.z; r.z = hv.z + (tt > 0.f ? tt : expm1f(tt));
    tt = dw * rstd * g.w + bb.w; r.w = hv.w + (tt > 0.f ? tt : expm1f(tt));

    *(float4*)(g_h + (size_t)n * 128 + c0) = r;
    if (final_out) *(float4*)(final_out + (size_t)n * 128 + c0) = r;
}

// ---------------- host orchestration ----------------------------------------
extern "C" void kernel_launch(void* const* d_in, const int* in_sizes, int n_in,
                              void* d_out, int out_size) {
    const float* x     = (const float*)d_in[0];
    const float* Wl    = (const float*)d_in[1];
    const float* Wr    = (const float*)d_in[2];
    const float* att   = (const float*)d_in[3];
    const float* bias  = (const float*)d_in[4];
    const float* gamma = (const float*)d_in[5];
    const float* beta  = (const float*)d_in[6];
    const int*   ei    = (const int*)d_in[7];
    float* out = (float*)d_out;

    void* deg_ptr = nullptr;
    void* h_ptr = nullptr;
    cudaGetSymbolAddress(&deg_ptr, g_deg);
    cudaGetSymbolAddress(&h_ptr, g_h);

    // build CSR (dst -> list of src), once per launch
    cudaMemsetAsync(deg_ptr, 0, NN * sizeof(int));
    hist_kernel<<<(EE + 255) / 256, 256>>>(ei);
    scan_kernel<<<1, SCAN_THREADS>>>();
    fill_kernel<<<(EE + 255) / 256, 256>>>(ei);

    const int gemm_grid = (NN + 127) / 128;   // 391
    const int node_grid = (NN + 7) / 8;

    for (int l = 0; l < LL; l++) {
        const float* X = (l == 0) ? x : (const float*)h_ptr;
        gemm_dual<<<gemm_grid, 256>>>(X, Wl + (size_t)l * DD * DD,
                                      Wr + (size_t)l * DD * DD);
        edge_csr<<<node_grid, 256>>>(att + l * HH * 16, bias + l * DD,
                                     gamma + l * DD, beta + l * DD, X,
                                     (l == LL - 1) ? out : nullptr);
    }
}

// round 9
// speedup vs baseline: 3.2049x; 1.0280x over previous
#include <cuda_runtime.h>
#include <cuda_bf16.h>
#include <math.h>
#include <stdint.h>

#define NN 50000
#define EE 800000
#define DD 128
#define HH 8
#define LL 3
#define SLOPE 0.2f
#define LN_EPS 1e-5f

#define XTILE 128
#define NTILES ((NN + XTILE - 1) / XTILE)   // 391
#define GEMM_CTAS 148

// ---------------- scratch (static device globals; no allocation allowed) ----
__device__ float g_h[NN * DD];        // evolving node features
__device__ float g_xl[NN * DD];       // h @ Wl
__device__ float g_xr[NN * DD];       // h @ Wr
__device__ int   g_deg[NN];
__device__ int   g_row[NN + 1];
__device__ int   g_cur[NN];
__device__ int   g_csr[EE];

// ---------------- helpers ---------------------------------------------------
__device__ __forceinline__ float lrelu(float x) { return x > 0.f ? x : SLOPE * x; }

// packed dual-fp32 FMA (Blackwell FFMA2; only reachable via PTX)
#define FMA_F32X2(d, a, b, c) \
    asm("fma.rn.f32x2 %0, %1, %2, %3;" : "=l"(d) : "l"(a), "l"(b), "l"(c))
#define PACK_DUP_F32X2(out, v) \
    asm("mov.b64 %0, {%1, %1};" : "=l"(out) : "f"(v))
#define UNPACK_F32X2(lo, hi, in) \
    asm("mov.b64 {%0, %1}, %2;" : "=f"(lo), "=f"(hi) : "l"(in))

// ---------------- CSR build (once per launch) --------------------------------
__global__ void hist_kernel(const int* __restrict__ ei) {
    int e = blockIdx.x * blockDim.x + threadIdx.x;
    if (e < EE) atomicAdd(&g_deg[__ldg(ei + EE + e)], 1);
}

#define SCAN_THREADS 1024
#define SCAN_PER 49
__global__ void scan_kernel() {
    int tid = threadIdx.x;
    int start = tid * SCAN_PER;
    int end = start + SCAN_PER; if (end > NN) end = NN;
    int s = 0;
    for (int i = start; i < end; i++) s += g_deg[i];

    int lane = tid & 31, wid = tid >> 5;
    int incl = s;
#pragma unroll
    for (int o = 1; o < 32; o <<= 1) {
        int u = __shfl_up_sync(0xffffffffu, incl, o);
        if (lane >= o) incl += u;
    }
    __shared__ int wsum[32];
    if (lane == 31) wsum[wid] = incl;
    __syncthreads();
    if (wid == 0) {
        int w = wsum[lane];
#pragma unroll
        for (int o = 1; o < 32; o <<= 1) {
            int u = __shfl_up_sync(0xffffffffu, w, o);
            if (lane >= o) w += u;
        }
        wsum[lane] = w;
    }
    __syncthreads();
    int excl = incl - s + (wid > 0 ? wsum[wid - 1] : 0);
    int run = excl;
    for (int i = start; i < end; i++) {
        g_row[i] = run;
        g_cur[i] = run;
        run += g_deg[i];
    }
    if (tid == 0) g_row[NN] = EE;
}

__global__ void fill_kernel(const int* __restrict__ ei) {
    int e = blockIdx.x * blockDim.x + threadIdx.x;
    if (e < EE) {
        int dst = __ldg(ei + EE + e);
        int p = atomicAdd(&g_cur[dst], 1);
        g_csr[p] = __ldg(ei + e);
    }
}

// ---------------- persistent dual GEMM via packed f32x2 FMA ------------------
// grid=148, block=256. W (both matrices, 128KB) resident in smem for the whole
// kernel; each CTA loops over 128-row tiles. 8x8 outputs/thread/matrix.
// smem layout (floats): Wls[128*128] | Wrs[128*128] | Xs[128*128] (transposed)
#define SMEM_FLOATS (3 * 128 * 128)

__global__ __launch_bounds__(256, 1) void gemm_persist(const float* __restrict__ X,
                                                       const float* __restrict__ Wl,
                                                       const float* __restrict__ Wr) {
    extern __shared__ float smem[];
    float* Wls = smem;              // [k*128 + c]
    float* Wrs = smem + 16384;
    float* Xs  = smem + 32768;      // [k*128 + row]  (transposed)

    int tid = threadIdx.x;
    int tx = tid & 15;    // col group: 8 cols = 4 f32x2 pairs
    int ty = tid >> 4;    // row group: 8 rows

    // ---- load both W matrices once (each thread: 16 float4 per matrix) ----
    for (int i = tid * 4; i < 16384; i += 1024) {
        *(float4*)(Wls + i) = *(const float4*)(Wl + i);
        *(float4*)(Wrs + i) = *(const float4*)(Wr + i);
    }
    __syncthreads();

    int xrow = tid & 127;
    int kq   = (tid >> 7) * 64;     // 0 or 64: half the k-range per thread

    for (int tile = blockIdx.x; tile < NTILES; tile += GEMM_CTAS) {
        int row0 = tile * XTILE;

        // ---- load X tile (128 rows x 128 k), store transposed ----
        {
            int gr = row0 + xrow;
#pragma unroll
            for (int k = 0; k < 64; k += 4) {
                float4 v = make_float4(0.f, 0.f, 0.f, 0.f);
                if (gr < NN) v = *(const float4*)(X + (size_t)gr * 128 + kq + k);
                Xs[(kq + k + 0) * 128 + xrow] = v.x;
                Xs[(kq + k + 1) * 128 + xrow] = v.y;
                Xs[(kq + k + 2) * 128 + xrow] = v.z;
                Xs[(kq + k + 3) * 128 + xrow] = v.w;
            }
        }
        __syncthreads();

        unsigned long long accL[8][4], accR[8][4];
#pragma unroll
        for (int i = 0; i < 8; i++)
#pragma unroll
            for (int j = 0; j < 4; j++) { accL[i][j] = 0ull; accR[i][j] = 0ull; }

#pragma unroll 4
        for (int kk = 0; kk < 128; kk++) {
            float4 a0 = *(const float4*)(&Xs[kk * 128 + ty * 8]);
            float4 a1 = *(const float4*)(&Xs[kk * 128 + ty * 8 + 4]);
            float a[8] = {a0.x, a0.y, a0.z, a0.w, a1.x, a1.y, a1.z, a1.w};
            ulonglong2 bl0 = *(const ulonglong2*)(&Wls[kk * 128 + tx * 8]);
            ulonglong2 bl1 = *(const ulonglong2*)(&Wls[kk * 128 + tx * 8 + 4]);
            ulonglong2 br0 = *(const ulonglong2*)(&Wrs[kk * 128 + tx * 8]);
            ulonglong2 br1 = *(const ulonglong2*)(&Wrs[kk * 128 + tx * 8 + 4]);
            unsigned long long bl[4] = {bl0.x, bl0.y, bl1.x, bl1.y};
            unsigned long long br[4] = {br0.x, br0.y, br1.x, br1.y};
#pragma unroll
            for (int i = 0; i < 8; i++) {
                unsigned long long aa;
                PACK_DUP_F32X2(aa, a[i]);
#pragma unroll
                for (int j = 0; j < 4; j++) {
                    FMA_F32X2(accL[i][j], aa, bl[j], accL[i][j]);
                    FMA_F32X2(accR[i][j], aa, br[j], accR[i][j]);
                }
            }
        }

        // ---- store results ----
#pragma unroll
        for (int i = 0; i < 8; i++) {
            int gr = row0 + ty * 8 + i;
            if (gr < NN) {
                float f[8];
#pragma unroll
                for (int j = 0; j < 4; j++) UNPACK_F32X2(f[j * 2], f[j * 2 + 1], accL[i][j]);
                *(float4*)(g_xl + (size_t)gr * 128 + tx * 8)     = make_float4(f[0], f[1], f[2], f[3]);
                *(float4*)(g_xl + (size_t)gr * 128 + tx * 8 + 4) = make_float4(f[4], f[5], f[6], f[7]);
#pragma unroll
                for (int j = 0; j < 4; j++) UNPACK_F32X2(f[j * 2], f[j * 2 + 1], accR[i][j]);
                *(float4*)(g_xr + (size_t)gr * 128 + tx * 8)     = make_float4(f[0], f[1], f[2], f[3]);
                *(float4*)(g_xr + (size_t)gr * 128 + tx * 8 + 4) = make_float4(f[4], f[5], f[6], f[7]);
            }
        }
        __syncthreads();   // protect Xs before next tile's overwrite
    }
}

// ---------------- CSR edge pass + softmax + LN + ELU + residual -------------
__global__ __launch_bounds__(256) void edge_csr(const float* __restrict__ att_l,
                                                const float* __restrict__ bias_l,
                                                const float* __restrict__ gamma_l,
                                                const float* __restrict__ beta_l,
                                                const float* __restrict__ resid,
                                                float* __restrict__ final_out) {
    int n = blockIdx.x * 8 + (threadIdx.x >> 5);
    if (n >= NN) return;
    int lane = threadIdx.x & 31;
    int c0 = lane * 4;

    float4 xr = *(const float4*)(g_xr + (size_t)n * 128 + c0);
    float4 t  = *(const float4*)(att_l + c0);

    // self-loop
    float4 a = *(const float4*)(g_xl + (size_t)n * 128 + c0);
    float s = lrelu(a.x + xr.x) * t.x + lrelu(a.y + xr.y) * t.y +
              lrelu(a.z + xr.z) * t.z + lrelu(a.w + xr.w) * t.w;
    s += __shfl_xor_sync(0xffffffffu, s, 1);
    s += __shfl_xor_sync(0xffffffffu, s, 2);
    float v = __expf(s);
    float4 acc = make_float4(v * a.x, v * a.y, v * a.z, v * a.w);
    float denom = v;

    int i = g_row[n];
    int endi = g_row[n + 1];
    for (; i + 1 < endi; i += 2) {
        int s0 = __ldg(g_csr + i);
        int s1 = __ldg(g_csr + i + 1);
        float4 a0 = *(const float4*)(g_xl + (size_t)s0 * 128 + c0);
        float4 a1 = *(const float4*)(g_xl + (size_t)s1 * 128 + c0);
        float l0 = lrelu(a0.x + xr.x) * t.x + lrelu(a0.y + xr.y) * t.y +
                   lrelu(a0.z + xr.z) * t.z + lrelu(a0.w + xr.w) * t.w;
        float l1 = lrelu(a1.x + xr.x) * t.x + lrelu(a1.y + xr.y) * t.y +
                   lrelu(a1.z + xr.z) * t.z + lrelu(a1.w + xr.w) * t.w;
        l0 += __shfl_xor_sync(0xffffffffu, l0, 1);
        l0 += __shfl_xor_sync(0xffffffffu, l0, 2);
        l1 += __shfl_xor_sync(0xffffffffu, l1, 1);
        l1 += __shfl_xor_sync(0xffffffffu, l1, 2);
        float v0 = __expf(l0);
        float v1 = __expf(l1);
        acc.x += v0 * a0.x + v1 * a1.x;
        acc.y += v0 * a0.y + v1 * a1.y;
        acc.z += v0 * a0.z + v1 * a1.z;
        acc.w += v0 * a0.w + v1 * a1.w;
        denom += v0 + v1;
    }
    if (i < endi) {
        int s0 = __ldg(g_csr + i);
        float4 a0 = *(const float4*)(g_xl + (size_t)s0 * 128 + c0);
        float l0 = lrelu(a0.x + xr.x) * t.x + lrelu(a0.y + xr.y) * t.y +
                   lrelu(a0.z + xr.z) * t.z + lrelu(a0.w + xr.w) * t.w;
        l0 += __shfl_xor_sync(0xffffffffu, l0, 1);
        l0 += __shfl_xor_sync(0xffffffffu, l0, 2);
        float v0 = __expf(l0);
        acc.x += v0 * a0.x;
        acc.y += v0 * a0.y;
        acc.z += v0 * a0.z;
        acc.w += v0 * a0.w;
        denom += v0;
    }

    float inv_d = 1.f / denom;
    float4 bi = *(const float4*)(bias_l + c0);
    float4 y;
    y.x = acc.x * inv_d + bi.x;
    y.y = acc.y * inv_d + bi.y;
    y.z = acc.z * inv_d + bi.z;
    y.w = acc.w * inv_d + bi.w;

    float sum = y.x + y.y + y.z + y.w;
#pragma unroll
    for (int o = 16; o; o >>= 1) sum += __shfl_xor_sync(0xffffffffu, sum, o);
    float mu = sum * (1.f / 128.f);

    float dx = y.x - mu, dy = y.y - mu, dz = y.z - mu, dw = y.w - mu;
    float vs = dx * dx + dy * dy + dz * dz + dw * dw;
#pragma unroll
    for (int o = 16; o; o >>= 1) vs += __shfl_xor_sync(0xffffffffu, vs, o);
    float rstd = rsqrtf(vs * (1.f / 128.f) + LN_EPS);

    float4 g  = *(const float4*)(gamma_l + c0);
    float4 bb = *(const float4*)(beta_l + c0);
    float4 hv = *(const float4*)(resid + (size_t)n * 128 + c0);

    float tt;
    float4 r;
    tt = dx * rstd * g.x + bb.x; r.x = hv.x + (tt > 0.f ? tt : expm1f(tt));
    tt = dy * rstd * g.y + bb.y; r.y = hv.y + (tt > 0.f ? tt : expm1f(tt));
    tt = dz * rstd * g.z + bb.z; r.z = hv.z + (tt > 0.f ? tt : expm1f(tt));
    tt = dw * rstd * g.w + bb.w; r.w = hv.w + (tt > 0.f ? tt : expm1f(tt));

    *(float4*)(g_h + (size_t)n * 128 + c0) = r;
    if (final_out) *(float4*)(final_out + (size_t)n * 128 + c0) = r;
}

// ---------------- host orchestration ----------------------------------------
extern "C" void kernel_launch(void* const* d_in, const int* in_sizes, int n_in,
                              void* d_out, int out_size) {
    const float* x     = (const float*)d_in[0];
    const float* Wl    = (const float*)d_in[1];
    const float* Wr    = (const float*)d_in[2];
    const float* att   = (const float*)d_in[3];
    const float* bias  = (const float*)d_in[4];
    const float* gamma = (const float*)d_in[5];
    const float* beta  = (const float*)d_in[6];
    const int*   ei    = (const int*)d_in[7];
    float* out = (float*)d_out;

    void* deg_ptr = nullptr;
    void* h_ptr = nullptr;
    cudaGetSymbolAddress(&deg_ptr, g_deg);
    cudaGetSymbolAddress(&h_ptr, g_h);

    const int smem_bytes = SMEM_FLOATS * sizeof(float);   // 196608
    cudaFuncSetAttribute(gemm_persist,
                         cudaFuncAttributeMaxDynamicSharedMemorySize, smem_bytes);

    // build CSR (dst -> list of src), once per launch
    cudaMemsetAsync(deg_ptr, 0, NN * sizeof(int));
    hist_kernel<<<(EE + 255) / 256, 256>>>(ei);
    scan_kernel<<<1, SCAN_THREADS>>>();
    fill_kernel<<<(EE + 255) / 256, 256>>>(ei);

    const int node_grid = (NN + 7) / 8;

    for (int l = 0; l < LL; l++) {
        const float* X = (l == 0) ? x : (const float*)h_ptr;
        gemm_persist<<<GEMM_CTAS, 256, smem_bytes>>>(X, Wl + (size_t)l * DD * DD,
                                                     Wr + (size_t)l * DD * DD);
        edge_csr<<<node_grid, 256>>>(att + l * HH * 16, bias + l * DD,
                                     gamma + l * DD, beta + l * DD, X,
                                     (l == LL - 1) ? out : nullptr);
    }
}

// round 10
// speedup vs baseline: 3.2740x; 1.0216x over previous
#include <cuda_runtime.h>
#include <cuda_bf16.h>
#include <math.h>
#include <stdint.h>

#define NN 50000
#define EE 800000
#define DD 128
#define HH 8
#define LL 3
#define SLOPE 0.2f
#define LN_EPS 1e-5f

#define XTILE 128
#define NTILES ((NN + XTILE - 1) / XTILE)   // 391
#define GEMM_CTAS 148

// ---------------- scratch (static device globals; no allocation allowed) ----
__device__ float g_h[NN * DD];        // evolving node features
__device__ float g_xl[NN * DD];       // h @ Wl
__device__ float g_xr[NN * DD];       // h @ Wr
__device__ int   g_deg[NN];
__device__ int   g_row[NN + 1];
__device__ int   g_cur[NN];
__device__ int   g_csr[EE];

// ---------------- helpers ---------------------------------------------------
__device__ __forceinline__ float lrelu(float x) { return x > 0.f ? x : SLOPE * x; }

// packed dual-fp32 FMA (Blackwell FFMA2; only reachable via PTX)
#define FMA_F32X2(d, a, b, c) \
    asm("fma.rn.f32x2 %0, %1, %2, %3;" : "=l"(d) : "l"(a), "l"(b), "l"(c))
#define PACK_DUP_F32X2(out, v) \
    asm("mov.b64 %0, {%1, %1};" : "=l"(out) : "f"(v))
#define UNPACK_F32X2(lo, hi, in) \
    asm("mov.b64 {%0, %1}, %2;" : "=f"(lo), "=f"(hi) : "l"(in))

// ---------------- CSR build (once per launch) --------------------------------
__global__ void hist_kernel(const int* __restrict__ ei) {
    int e = blockIdx.x * blockDim.x + threadIdx.x;
    if (e < EE) atomicAdd(&g_deg[__ldg(ei + EE + e)], 1);
}

#define SCAN_THREADS 1024
#define SCAN_PER 49
__global__ void scan_kernel() {
    int tid = threadIdx.x;
    int start = tid * SCAN_PER;
    int end = start + SCAN_PER; if (end > NN) end = NN;
    int s = 0;
    for (int i = start; i < end; i++) s += g_deg[i];

    int lane = tid & 31, wid = tid >> 5;
    int incl = s;
#pragma unroll
    for (int o = 1; o < 32; o <<= 1) {
        int u = __shfl_up_sync(0xffffffffu, incl, o);
        if (lane >= o) incl += u;
    }
    __shared__ int wsum[32];
    if (lane == 31) wsum[wid] = incl;
    __syncthreads();
    if (wid == 0) {
        int w = wsum[lane];
#pragma unroll
        for (int o = 1; o < 32; o <<= 1) {
            int u = __shfl_up_sync(0xffffffffu, w, o);
            if (lane >= o) w += u;
        }
        wsum[lane] = w;
    }
    __syncthreads();
    int excl = incl - s + (wid > 0 ? wsum[wid - 1] : 0);
    int run = excl;
    for (int i = start; i < end; i++) {
        g_row[i] = run;
        g_cur[i] = run;
        run += g_deg[i];
    }
    if (tid == 0) g_row[NN] = EE;
}

__global__ void fill_kernel(const int* __restrict__ ei) {
    int e = blockIdx.x * blockDim.x + threadIdx.x;
    if (e < EE) {
        int dst = __ldg(ei + EE + e);
        int p = atomicAdd(&g_cur[dst], 1);
        g_csr[p] = __ldg(ei + e);
    }
}

// ---------------- persistent dual GEMM, 512 thr, matrix-split ---------------
// grid=148, block=512. Threads [0,256) compute xl (read Wls only);
// threads [256,512) compute xr (read Wrs only). 8x8 tile per thread.
// smem: Wls[16384] | Wrs[16384] | Xs[16384] (transposed) = 192KB
#define SMEM_FLOATS (3 * 128 * 128)

__global__ __launch_bounds__(512, 1) void gemm_persist(const float* __restrict__ X,
                                                       const float* __restrict__ Wl,
                                                       const float* __restrict__ Wr) {
    extern __shared__ float smem[];
    float* Wls = smem;              // [k*128 + c]
    float* Wrs = smem + 16384;
    float* Xs  = smem + 32768;      // [k*128 + row]  (transposed)

    int tid = threadIdx.x;
    int half = tid >> 8;            // 0: xl, 1: xr
    int htid = tid & 255;
    int tx = htid & 15;             // col group: 8 cols = 4 f32x2 pairs
    int ty = htid >> 4;             // row group: 8 rows

    const float* Ws = half ? Wrs : Wls;
    float* Yout = half ? g_xr : g_xl;

    // ---- load both W matrices once ----
    for (int i = tid * 4; i < 16384; i += 2048) {
        *(float4*)(Wls + i) = *(const float4*)(Wl + i);
        *(float4*)(Wrs + i) = *(const float4*)(Wr + i);
    }
    __syncthreads();

    int xrow = tid & 127;
    int kq   = (tid >> 7) * 32;     // 0..96: quarter of the k-range per thread

    for (int tile = blockIdx.x; tile < NTILES; tile += GEMM_CTAS) {
        int row0 = tile * XTILE;

        // ---- load X tile (128 rows x 128 k), store transposed ----
        {
            int gr = row0 + xrow;
#pragma unroll
            for (int k = 0; k < 32; k += 4) {
                float4 v = make_float4(0.f, 0.f, 0.f, 0.f);
                if (gr < NN) v = *(const float4*)(X + (size_t)gr * 128 + kq + k);
                Xs[(kq + k + 0) * 128 + xrow] = v.x;
                Xs[(kq + k + 1) * 128 + xrow] = v.y;
                Xs[(kq + k + 2) * 128 + xrow] = v.z;
                Xs[(kq + k + 3) * 128 + xrow] = v.w;
            }
        }
        __syncthreads();

        unsigned long long acc[8][4];
#pragma unroll
        for (int i = 0; i < 8; i++)
#pragma unroll
            for (int j = 0; j < 4; j++) acc[i][j] = 0ull;

#pragma unroll 4
        for (int kk = 0; kk < 128; kk++) {
            float4 a0 = *(const float4*)(&Xs[kk * 128 + ty * 8]);
            float4 a1 = *(const float4*)(&Xs[kk * 128 + ty * 8 + 4]);
            float a[8] = {a0.x, a0.y, a0.z, a0.w, a1.x, a1.y, a1.z, a1.w};
            ulonglong2 b0 = *(const ulonglong2*)(&Ws[kk * 128 + tx * 8]);
            ulonglong2 b1 = *(const ulonglong2*)(&Ws[kk * 128 + tx * 8 + 4]);
            unsigned long long b[4] = {b0.x, b0.y, b1.x, b1.y};
#pragma unroll
            for (int i = 0; i < 8; i++) {
                unsigned long long aa;
                PACK_DUP_F32X2(aa, a[i]);
#pragma unroll
                for (int j = 0; j < 4; j++)
                    FMA_F32X2(acc[i][j], aa, b[j], acc[i][j]);
            }
        }

        // ---- store results ----
#pragma unroll
        for (int i = 0; i < 8; i++) {
            int gr = row0 + ty * 8 + i;
            if (gr < NN) {
                float f[8];
#pragma unroll
                for (int j = 0; j < 4; j++) UNPACK_F32X2(f[j * 2], f[j * 2 + 1], acc[i][j]);
                *(float4*)(Yout + (size_t)gr * 128 + tx * 8)     = make_float4(f[0], f[1], f[2], f[3]);
                *(float4*)(Yout + (size_t)gr * 128 + tx * 8 + 4) = make_float4(f[4], f[5], f[6], f[7]);
            }
        }
        __syncthreads();   // protect Xs before next tile's overwrite
    }
}

// ---------------- CSR edge pass + softmax + LN + ELU + residual -------------
__global__ __launch_bounds__(256) void edge_csr(const float* __restrict__ att_l,
                                                const float* __restrict__ bias_l,
                                                const float* __restrict__ gamma_l,
                                                const float* __restrict__ beta_l,
                                                const float* __restrict__ resid,
                                                float* __restrict__ final_out) {
    int n = blockIdx.x * 8 + (threadIdx.x >> 5);
    if (n >= NN) return;
    int lane = threadIdx.x & 31;
    int c0 = lane * 4;

    float4 xr = *(const float4*)(g_xr + (size_t)n * 128 + c0);
    float4 t  = *(const float4*)(att_l + c0);

    // self-loop
    float4 a = *(const float4*)(g_xl + (size_t)n * 128 + c0);
    float s = lrelu(a.x + xr.x) * t.x + lrelu(a.y + xr.y) * t.y +
              lrelu(a.z + xr.z) * t.z + lrelu(a.w + xr.w) * t.w;
    s += __shfl_xor_sync(0xffffffffu, s, 1);
    s += __shfl_xor_sync(0xffffffffu, s, 2);
    float v = __expf(s);
    float4 acc = make_float4(v * a.x, v * a.y, v * a.z, v * a.w);
    float denom = v;

    int i = g_row[n];
    int endi = g_row[n + 1];

    // 4-way unrolled: 4 independent gathers in flight
    for (; i + 3 < endi; i += 4) {
        int s0 = __ldg(g_csr + i);
        int s1 = __ldg(g_csr + i + 1);
        int s2 = __ldg(g_csr + i + 2);
        int s3 = __ldg(g_csr + i + 3);
        float4 a0 = *(const float4*)(g_xl + (size_t)s0 * 128 + c0);
        float4 a1 = *(const float4*)(g_xl + (size_t)s1 * 128 + c0);
        float4 a2 = *(const float4*)(g_xl + (size_t)s2 * 128 + c0);
        float4 a3 = *(const float4*)(g_xl + (size_t)s3 * 128 + c0);
        float l0 = lrelu(a0.x + xr.x) * t.x + lrelu(a0.y + xr.y) * t.y +
                   lrelu(a0.z + xr.z) * t.z + lrelu(a0.w + xr.w) * t.w;
        float l1 = lrelu(a1.x + xr.x) * t.x + lrelu(a1.y + xr.y) * t.y +
                   lrelu(a1.z + xr.z) * t.z + lrelu(a1.w + xr.w) * t.w;
        float l2 = lrelu(a2.x + xr.x) * t.x + lrelu(a2.y + xr.y) * t.y +
                   lrelu(a2.z + xr.z) * t.z + lrelu(a2.w + xr.w) * t.w;
        float l3 = lrelu(a3.x + xr.x) * t.x + lrelu(a3.y + xr.y) * t.y +
                   lrelu(a3.z + xr.z) * t.z + lrelu(a3.w + xr.w) * t.w;
        l0 += __shfl_xor_sync(0xffffffffu, l0, 1);
        l0 += __shfl_xor_sync(0xffffffffu, l0, 2);
        l1 += __shfl_xor_sync(0xffffffffu, l1, 1);
        l1 += __shfl_xor_sync(0xffffffffu, l1, 2);
        l2 += __shfl_xor_sync(0xffffffffu, l2, 1);
        l2 += __shfl_xor_sync(0xffffffffu, l2, 2);
        l3 += __shfl_xor_sync(0xffffffffu, l3, 1);
        l3 += __shfl_xor_sync(0xffffffffu, l3, 2);
        float v0 = __expf(l0);
        float v1 = __expf(l1);
        float v2 = __expf(l2);
        float v3 = __expf(l3);
        acc.x += v0 * a0.x + v1 * a1.x + v2 * a2.x + v3 * a3.x;
        acc.y += v0 * a0.y + v1 * a1.y + v2 * a2.y + v3 * a3.y;
        acc.z += v0 * a0.z + v1 * a1.z + v2 * a2.z + v3 * a3.z;
        acc.w += v0 * a0.w + v1 * a1.w + v2 * a2.w + v3 * a3.w;
        denom += v0 + v1 + v2 + v3;
    }
    for (; i < endi; i++) {
        int s0 = __ldg(g_csr + i);
        float4 a0 = *(const float4*)(g_xl + (size_t)s0 * 128 + c0);
        float l0 = lrelu(a0.x + xr.x) * t.x + lrelu(a0.y + xr.y) * t.y +
                   lrelu(a0.z + xr.z) * t.z + lrelu(a0.w + xr.w) * t.w;
        l0 += __shfl_xor_sync(0xffffffffu, l0, 1);
        l0 += __shfl_xor_sync(0xffffffffu, l0, 2);
        float v0 = __expf(l0);
        acc.x += v0 * a0.x;
        acc.y += v0 * a0.y;
        acc.z += v0 * a0.z;
        acc.w += v0 * a0.w;
        denom += v0;
    }

    float inv_d = 1.f / denom;
    float4 bi = *(const float4*)(bias_l + c0);
    float4 y;
    y.x = acc.x * inv_d + bi.x;
    y.y = acc.y * inv_d + bi.y;
    y.z = acc.z * inv_d + bi.z;
    y.w = acc.w * inv_d + bi.w;

    float sum = y.x + y.y + y.z + y.w;
#pragma unroll
    for (int o = 16; o; o >>= 1) sum += __shfl_xor_sync(0xffffffffu, sum, o);
    float mu = sum * (1.f / 128.f);

    float dx = y.x - mu, dy = y.y - mu, dz = y.z - mu, dw = y.w - mu;
    float vs = dx * dx + dy * dy + dz * dz + dw * dw;
#pragma unroll
    for (int o = 16; o; o >>= 1) vs += __shfl_xor_sync(0xffffffffu, vs, o);
    float rstd = rsqrtf(vs * (1.f / 128.f) + LN_EPS);

    float4 g  = *(const float4*)(gamma_l + c0);
    float4 bb = *(const float4*)(beta_l + c0);
    float4 hv = *(const float4*)(resid + (size_t)n * 128 + c0);

    float tt;
    float4 r;
    tt = dx * rstd * g.x + bb.x; r.x = hv.x + (tt > 0.f ? tt : expm1f(tt));
    tt = dy * rstd * g.y + bb.y; r.y = hv.y + (tt > 0.f ? tt : expm1f(tt));
    tt = dz * rstd * g.z + bb.z; r.z = hv.z + (tt > 0.f ? tt : expm1f(tt));
    tt = dw * rstd * g.w + bb.w; r.w = hv.w + (tt > 0.f ? tt : expm1f(tt));

    *(float4*)(g_h + (size_t)n * 128 + c0) = r;
    if (final_out) *(float4*)(final_out + (size_t)n * 128 + c0) = r;
}

// ---------------- host orchestration ----------------------------------------
extern "C" void kernel_launch(void* const* d_in, const int* in_sizes, int n_in,
                              void* d_out, int out_size) {
    const float* x     = (const float*)d_in[0];
    const float* Wl    = (const float*)d_in[1];
    const float* Wr    = (const float*)d_in[2];
    const float* att   = (const float*)d_in[3];
    const float* bias  = (const float*)d_in[4];
    const float* gamma = (const float*)d_in[5];
    const float* beta  = (const float*)d_in[6];
    const int*   ei    = (const int*)d_in[7];
    float* out = (float*)d_out;

    void* deg_ptr = nullptr;
    void* h_ptr = nullptr;
    cudaGetSymbolAddress(&deg_ptr, g_deg);
    cudaGetSymbolAddress(&h_ptr, g_h);

    const int smem_bytes = SMEM_FLOATS * sizeof(float);   // 196608
    cudaFuncSetAttribute(gemm_persist,
                         cudaFuncAttributeMaxDynamicSharedMemorySize, smem_bytes);

    // build CSR (dst -> list of src), once per launch
    cudaMemsetAsync(deg_ptr, 0, NN * sizeof(int));
    hist_kernel<<<(EE + 255) / 256, 256>>>(ei);
    scan_kernel<<<1, SCAN_THREADS>>>();
    fill_kernel<<<(EE + 255) / 256, 256>>>(ei);

    const int node_grid = (NN + 7) / 8;

    for (int l = 0; l < LL; l++) {
        const float* X = (l == 0) ? x : (const float*)h_ptr;
        gemm_persist<<<GEMM_CTAS, 512, smem_bytes>>>(X, Wl + (size_t)l * DD * DD,
                                                     Wr + (size_t)l * DD * DD);
        edge_csr<<<node_grid, 256>>>(att + l * HH * 16, bias + l * DD,
                                     gamma + l * DD, beta + l * DD, X,
                                     (l == LL - 1) ? out : nullptr);
    }
}